// round 14
// baseline (speedup 1.0000x reference)
#include <cuda_runtime.h>
#include <cuda_bf16.h>
#include <math.h>
#include <stdint.h>

#define Nn   50000
#define Ee   200000
#define EP   (Ee + Nn)      // 250000 edges incl. self loops
#define Gg   64
#define Hh   4
#define Cch  256
#define DH   1024
#define DIN  768

// ---------------- scratch (device globals; no allocation allowed) ----------
__device__ float g_h  [(size_t)Nn * DH];   // x @ W  (current layer)
__device__ float g_x  [(size_t)Nn * DH];   // layer-2 output (post ELU)
__device__ float g_esrc[Nn * Hh];
__device__ float g_edst[Nn * Hh];
__device__ float g_sum [Gg * DH];
__device__ float g_max [Gg * DH];
__device__ int   g_cnt [Gg];
__device__ float g_pool[Gg * 2 * DH];
__device__ float g_fc1 [Gg * 512];
__device__ float g_fc2 [Gg * 256];
// transposed + hi/lo split weights: Wt[n][k]
__device__ __nv_bfloat16 g_wthi[(size_t)DH * DH];
__device__ __nv_bfloat16 g_wtlo[(size_t)DH * DH];
// hi/lo split activations (GEMM A operand)
__device__ __nv_bfloat16 g_ahi[(size_t)Nn * DH];
__device__ __nv_bfloat16 g_alo[(size_t)Nn * DH];
// CSR by destination
__device__ int g_deg[Nn];
__device__ int g_off[Nn + 1];
__device__ int g_cur[Nn];
__device__ int g_csr[EP];          // src node per slot

// ---------------- helpers ---------------------------------------------------
__device__ __forceinline__ float lrelu(float x) { return x > 0.f ? x : 0.2f * x; }
__device__ __forceinline__ float eluf (float x) { return x > 0.f ? x : expm1f(x); }

__device__ __forceinline__ void atomicMaxF(float* a, float v) {
    if (v >= 0.f) atomicMax((int*)a, __float_as_int(v));
    else          atomicMin((unsigned int*)a, __float_as_uint(v));
}

__device__ __forceinline__ uint32_t smem_u32(const void* p) {
    uint32_t a;
    asm("{ .reg .u64 t; cvta.to.shared.u64 t, %1; cvt.u32.u64 %0, t; }"
        : "=r"(a) : "l"(p));
    return a;
}

__device__ __forceinline__ void ldm4(uint32_t* r, uint32_t addr) {
    asm volatile("ldmatrix.sync.aligned.m8n8.x4.shared.b16 {%0,%1,%2,%3}, [%4];"
                 : "=r"(r[0]), "=r"(r[1]), "=r"(r[2]), "=r"(r[3]) : "r"(addr));
}

__device__ __forceinline__ void mma16816(float* c, const uint32_t* a,
                                         uint32_t b0, uint32_t b1) {
    asm volatile(
        "mma.sync.aligned.m16n8k16.row.col.f32.bf16.bf16.f32 "
        "{%0,%1,%2,%3}, {%4,%5,%6,%7}, {%8,%9}, {%0,%1,%2,%3};"
        : "+f"(c[0]), "+f"(c[1]), "+f"(c[2]), "+f"(c[3])
        : "r"(a[0]), "r"(a[1]), "r"(a[2]), "r"(a[3]), "r"(b0), "r"(b1));
}

#define CPA16(dst, src) \
    asm volatile("cp.async.cg.shared.global [%0], [%1], 16;" \
                 :: "r"(dst), "l"(src) : "memory")
#define CPA16Z(dst, src, szr) \
    asm volatile("cp.async.cg.shared.global [%0], [%1], 16, %2;" \
                 :: "r"(dst), "l"(src), "r"(szr) : "memory")

// ---------------- CSR build --------------------------------------------------
__global__ void csr_zero_kernel(int* __restrict__ deg, int* __restrict__ cur) {
    int i = blockIdx.x * 256 + threadIdx.x;
    if (i < Nn) { deg[i] = 0; cur[i] = 0; }
}

__global__ void csr_hist_kernel(const int* __restrict__ dst, int* __restrict__ deg) {
    int i = blockIdx.x * 256 + threadIdx.x;
    if (i >= EP) return;
    int d_ = (i < Ee) ? dst[i] : (i - Ee);
    atomicAdd(&deg[d_], 1);
}

__global__ void csr_scan_kernel(const int* __restrict__ deg, int* __restrict__ off) {
    __shared__ int bs[1024];
    const int t = threadIdx.x;
    const int per = (Nn + 1023) / 1024;        // 49
    const int b0 = t * per;
    int loc = 0;
    for (int i = 0; i < per; i++) {
        int idx = b0 + i;
        if (idx < Nn) loc += deg[idx];
    }
    bs[t] = loc;
    __syncthreads();
    for (int o = 1; o < 1024; o <<= 1) {
        int v = (t >= o) ? bs[t - o] : 0;
        __syncthreads();
        bs[t] += v;
        __syncthreads();
    }
    int run = t ? bs[t - 1] : 0;
    for (int i = 0; i < per; i++) {
        int idx = b0 + i;
        if (idx < Nn) { off[idx] = run; run += deg[idx]; }
    }
    if (t == 1023) off[Nn] = run;
}

__global__ void csr_fill_kernel(const int* __restrict__ src, const int* __restrict__ dst,
                                const int* __restrict__ off, int* __restrict__ cur,
                                int* __restrict__ csr) {
    int i = blockIdx.x * 256 + threadIdx.x;
    if (i >= EP) return;
    int s_, d_;
    if (i < Ee) { s_ = src[i]; d_ = dst[i]; } else { s_ = d_ = i - Ee; }
    int pos = off[d_] + atomicAdd(&cur[d_], 1);
    csr[pos] = s_;
}

// ---------------- splits -----------------------------------------------------
__global__ void wsplit_kernel(const float* __restrict__ W,
                              __nv_bfloat16* __restrict__ hi,
                              __nv_bfloat16* __restrict__ lo, int K) {
    int idx = blockIdx.x * 256 + threadIdx.x;
    if (idx >= K * DH) return;
    int n = idx & (DH - 1), k = idx >> 10;   // W[k][n], row-major (K, 1024)
    float v = W[idx];
    __nv_bfloat16 h = __float2bfloat16(v);
    hi[(size_t)n * K + k] = h;
    lo[(size_t)n * K + k] = __float2bfloat16(v - __bfloat162float(h));
}

__global__ void asplit_kernel(const float* __restrict__ A,
                              __nv_bfloat16* __restrict__ hi,
                              __nv_bfloat16* __restrict__ lo, int total) {
    int idx = blockIdx.x * 256 + threadIdx.x;
    if (idx >= total) return;
    float v = A[idx];
    __nv_bfloat16 h = __float2bfloat16(v);
    hi[idx] = h;
    lo[idx] = __float2bfloat16(v - __bfloat162float(h));
}

// ---------------- tensor-core GEMM via mma.sync (bf16x3 split) --------------
// C[M,1024] = A[M,K] @ W[K,1024]; fused attention-score epilogue:
// col tile == one head (N-tile 256), so this CTA computes es/ed for its rows.
#define GEMM_SMEM (2 * 98304)

__global__ __launch_bounds__(512, 1)
void gemm_mma_kernel(const __nv_bfloat16* __restrict__ Ahi,
                     const __nv_bfloat16* __restrict__ Alo,
                     const __nv_bfloat16* __restrict__ Bhi,
                     const __nv_bfloat16* __restrict__ Blo,
                     float* __restrict__ C, int M, int K,
                     const float* __restrict__ asrc,
                     const float* __restrict__ adst,
                     float* __restrict__ es, float* __restrict__ ed) {
    extern __shared__ __align__(1024) char smem[];
    const int tid = threadIdx.x, wid = tid >> 5, lane = tid & 31;
    const int wm = wid & 3, wn = wid >> 2;
    const int lr = lane & 15, lh = lane >> 4;
    const int row0 = blockIdx.y * 128, col0 = blockIdx.x * 256;
    const int head = blockIdx.x;               // 256-wide col tile == head
    const uint32_t sb = smem_u32(smem);
    const int nc = K >> 6;

    float acc[2][8][4];
#pragma unroll
    for (int t = 0; t < 2; t++)
#pragma unroll
        for (int j = 0; j < 8; j++)
#pragma unroll
            for (int q = 0; q < 4; q++) acc[t][j][q] = 0.f;

    auto loadStage = [&](int ck) {
        uint32_t st = sb + (uint32_t)(ck & 1) * 98304u;
        const __nv_bfloat16* Ah = Ahi + (size_t)row0 * K + ck * 64;
        const __nv_bfloat16* Al = Alo + (size_t)row0 * K + ck * 64;
#pragma unroll
        for (int u = tid; u < 1024; u += 512) {
            int r = u >> 3, c = u & 7;
            uint32_t d = st + (uint32_t)(r * 128) + (uint32_t)((c ^ (r & 7)) << 4);
            uint32_t sz = (row0 + r < M) ? 16u : 0u;
            CPA16Z(d,          Ah + (size_t)r * K + c * 8, sz);
            CPA16Z(d + 16384u, Al + (size_t)r * K + c * 8, sz);
        }
        const __nv_bfloat16* Bh = Bhi + (size_t)col0 * K + ck * 64;
        const __nv_bfloat16* Bl = Blo + (size_t)col0 * K + ck * 64;
#pragma unroll
        for (int u = tid; u < 2048; u += 512) {
            int r = u >> 3, c = u & 7;
            uint32_t d = st + 32768u + (uint32_t)(r * 128) +
                         (uint32_t)((c ^ (r & 7)) << 4);
            CPA16(d,          Bh + (size_t)r * K + c * 8);
            CPA16(d + 32768u, Bl + (size_t)r * K + c * 8);
        }
        asm volatile("cp.async.commit_group;" ::: "memory");
    };

    auto compute = [&](int ck) {
        uint32_t base = sb + (uint32_t)(ck & 1) * 98304u;
#pragma unroll
        for (int ks = 0; ks < 4; ks++) {
            uint32_t c16 = (uint32_t)(ks * 2 + lh);
            uint32_t ah[2][4], al[2][4];
#pragma unroll
            for (int t = 0; t < 2; t++) {
                int row = wm * 32 + t * 16 + lr;
                uint32_t ad = base + (uint32_t)(row * 128) +
                              ((c16 ^ (uint32_t)(row & 7)) << 4);
                ldm4(ah[t], ad);
                ldm4(al[t], ad + 16384u);
            }
#pragma unroll
            for (int g = 0; g < 4; g++) {
                int row = wn * 64 + g * 16 + lr;
                uint32_t bd = base + 32768u + (uint32_t)(row * 128) +
                              ((c16 ^ (uint32_t)(row & 7)) << 4);
                uint32_t bh[4], bl[4];
                ldm4(bh, bd);
                ldm4(bl, bd + 32768u);
#pragma unroll
                for (int t = 0; t < 2; t++)
#pragma unroll
                    for (int o = 0; o < 2; o++) {
                        float* a4 = acc[t][g * 2 + o];
                        mma16816(a4, ah[t], bh[o], bh[o + 2]);   // hi*hi
                        mma16816(a4, al[t], bh[o], bh[o + 2]);   // lo*hi
                        mma16816(a4, ah[t], bl[o], bl[o + 2]);   // hi*lo
                    }
            }
        }
    };

    // ---- prologue ----
    loadStage(0);
    if (nc > 1) loadStage(1);
    asm volatile("cp.async.wait_group %0;" :: "n"(1) : "memory");
    __syncthreads();

    // ---- mainloop ----
    for (int c = 0; c < nc; ++c) {
        compute(c);
        __syncthreads();
        if (c + 1 < nc) {
            if (c + 2 < nc) {
                loadStage(c + 2);
                asm volatile("cp.async.wait_group %0;" :: "n"(1) : "memory");
            } else {
                asm volatile("cp.async.wait_group %0;" :: "n"(0) : "memory");
            }
            __syncthreads();
        }
    }

    // ---- epilogue: C store + fused per-head attention scores ----
    float* sred = (float*)smem;                 // [0:128) src, [128:256) dst
#pragma unroll
    for (int i = tid; i < 256; i += 512) sred[i] = 0.f;

    float psum[2][2] = {{0.f, 0.f}, {0.f, 0.f}};
    float pdum[2][2] = {{0.f, 0.f}, {0.f, 0.f}};
#pragma unroll
    for (int t = 0; t < 2; t++) {
        int m0 = row0 + wm * 32 + t * 16 + (lane >> 2);
#pragma unroll
        for (int j = 0; j < 8; j++) {
            int cloc = wn * 64 + j * 8 + (lane & 3) * 2;
            int col = col0 + cloc;
            if (m0 < M)
                *(float2*)(C + (size_t)m0 * DH + col) =
                    make_float2(acc[t][j][0], acc[t][j][1]);
            if (m0 + 8 < M)
                *(float2*)(C + (size_t)(m0 + 8) * DH + col) =
                    make_float2(acc[t][j][2], acc[t][j][3]);
            float a0 = asrc[head * Cch + cloc], a1 = asrc[head * Cch + cloc + 1];
            float d0 = adst[head * Cch + cloc], d1 = adst[head * Cch + cloc + 1];
            psum[t][0] += acc[t][j][0] * a0 + acc[t][j][1] * a1;
            psum[t][1] += acc[t][j][2] * a0 + acc[t][j][3] * a1;
            pdum[t][0] += acc[t][j][0] * d0 + acc[t][j][1] * d1;
            pdum[t][1] += acc[t][j][2] * d0 + acc[t][j][3] * d1;
        }
    }
    // reduce over the 4 lanes of each quad (lane&3)
#pragma unroll
    for (int t = 0; t < 2; t++)
#pragma unroll
        for (int r2 = 0; r2 < 2; r2++) {
            psum[t][r2] += __shfl_xor_sync(0xffffffffu, psum[t][r2], 1);
            psum[t][r2] += __shfl_xor_sync(0xffffffffu, psum[t][r2], 2);
            pdum[t][r2] += __shfl_xor_sync(0xffffffffu, pdum[t][r2], 1);
            pdum[t][r2] += __shfl_xor_sync(0xffffffffu, pdum[t][r2], 2);
        }
    __syncthreads();            // sred zero-fill visible; stage reads long done
    if ((lane & 3) == 0) {
#pragma unroll
        for (int t = 0; t < 2; t++)
#pragma unroll
            for (int r2 = 0; r2 < 2; r2++) {
                int rl = wm * 32 + t * 16 + r2 * 8 + (lane >> 2);
                atomicAdd(&sred[rl],       psum[t][r2]);
                atomicAdd(&sred[128 + rl], pdum[t][r2]);
            }
    }
    __syncthreads();
#pragma unroll
    for (int r2 = tid; r2 < 128; r2 += 512) {
        int n = row0 + r2;
        if (n < M) {
            es[n * Hh + head] = sred[r2];
            ed[n * Hh + head] = sred[128 + r2];
        }
    }
}

// ---------------- fused softmax + gather aggregation -------------------------
// one 256-thread block per destination node. CSR indices staged in smem and
// the gather unrolled x4 (independent loads) to raise memory-level parallelism.
__global__ __launch_bounds__(256)
void agg_kernel(const int* __restrict__ off, const int* __restrict__ csr,
                const float* __restrict__ es, const float* __restrict__ ed,
                const float* __restrict__ h, const float* __restrict__ bias,
                float* __restrict__ out,
                __nv_bfloat16* __restrict__ ohi, __nv_bfloat16* __restrict__ olo) {
    const int d = blockIdx.x;
    const int beg = off[d], end = off[d + 1];
    const int deg = end - beg;
    const int tid = threadIdx.x, wid = tid >> 5, lane = tid & 31;

    __shared__ float sm[4], ss[4];
    __shared__ float al[4][64];
    __shared__ int   sidx[64];

    if (wid < 4) {
        const float edv = ed[d * 4 + wid];
        float mx = -INFINITY;
        for (int i = beg + lane; i < end; i += 32) {
            int s_ = csr[i];
            mx = fmaxf(mx, lrelu(es[s_ * 4 + wid] + edv));
        }
#pragma unroll
        for (int o = 16; o; o >>= 1)
            mx = fmaxf(mx, __shfl_xor_sync(0xffffffffu, mx, o));
        float su = 0.f;
        for (int i = beg + lane; i < end; i += 32) {
            int s_ = csr[i];
            su += expf(lrelu(es[s_ * 4 + wid] + edv) - mx);
        }
#pragma unroll
        for (int o = 16; o; o >>= 1)
            su += __shfl_xor_sync(0xffffffffu, su, o);
        if (lane == 0) { sm[wid] = mx; ss[wid] = su; }
    }
    __syncthreads();

    const int head = tid >> 6;
    float4 acc = make_float4(0.f, 0.f, 0.f, 0.f);

    for (int c0 = 0; c0 < deg; c0 += 64) {
        {
            int j = tid & 63, hh = tid >> 6;
            if (c0 + j < deg) {
                int s_ = csr[beg + c0 + j];
                float e = lrelu(es[s_ * 4 + hh] + ed[d * 4 + hh]);
                al[hh][j] = expf(e - sm[hh]) / (ss[hh] + 1e-16f);
                if (hh == 0) sidx[j] = s_;
            }
        }
        __syncthreads();
        int lim = min(64, deg - c0);
        int j = 0;
        for (; j + 4 <= lim; j += 4) {
            int s0 = sidx[j], s1 = sidx[j + 1], s2 = sidx[j + 2], s3 = sidx[j + 3];
            float4 v0 = *(const float4*)(h + (size_t)s0 * DH + tid * 4);
            float4 v1 = *(const float4*)(h + (size_t)s1 * DH + tid * 4);
            float4 v2 = *(const float4*)(h + (size_t)s2 * DH + tid * 4);
            float4 v3 = *(const float4*)(h + (size_t)s3 * DH + tid * 4);
            float a0 = al[head][j],     a1 = al[head][j + 1];
            float a2 = al[head][j + 2], a3 = al[head][j + 3];
            acc.x = fmaf(a0, v0.x, acc.x); acc.y = fmaf(a0, v0.y, acc.y);
            acc.z = fmaf(a0, v0.z, acc.z); acc.w = fmaf(a0, v0.w, acc.w);
            acc.x = fmaf(a1, v1.x, acc.x); acc.y = fmaf(a1, v1.y, acc.y);
            acc.z = fmaf(a1, v1.z, acc.z); acc.w = fmaf(a1, v1.w, acc.w);
            acc.x = fmaf(a2, v2.x, acc.x); acc.y = fmaf(a2, v2.y, acc.y);
            acc.z = fmaf(a2, v2.z, acc.z); acc.w = fmaf(a2, v2.w, acc.w);
            acc.x = fmaf(a3, v3.x, acc.x); acc.y = fmaf(a3, v3.y, acc.y);
            acc.z = fmaf(a3, v3.z, acc.z); acc.w = fmaf(a3, v3.w, acc.w);
        }
        for (; j < lim; j++) {
            int s_ = sidx[j];
            float a = al[head][j];
            float4 v = *(const float4*)(h + (size_t)s_ * DH + tid * 4);
            acc.x = fmaf(a, v.x, acc.x);
            acc.y = fmaf(a, v.y, acc.y);
            acc.z = fmaf(a, v.z, acc.z);
            acc.w = fmaf(a, v.w, acc.w);
        }
        __syncthreads();
    }

    float4 bb = *(const float4*)(bias + tid * 4);
    acc.x = eluf(acc.x + bb.x);
    acc.y = eluf(acc.y + bb.y);
    acc.z = eluf(acc.z + bb.z);
    acc.w = eluf(acc.w + bb.w);

    if (ohi) {
        __nv_bfloat162 h0 = __floats2bfloat162_rn(acc.x, acc.y);
        __nv_bfloat162 h1 = __floats2bfloat162_rn(acc.z, acc.w);
        __nv_bfloat162 l0 = __floats2bfloat162_rn(acc.x - __bfloat162float(h0.x),
                                                  acc.y - __bfloat162float(h0.y));
        __nv_bfloat162 l1 = __floats2bfloat162_rn(acc.z - __bfloat162float(h1.x),
                                                  acc.w - __bfloat162float(h1.y));
        *(__nv_bfloat162*)(ohi + (size_t)d * DH + tid * 4)     = h0;
        *(__nv_bfloat162*)(ohi + (size_t)d * DH + tid * 4 + 2) = h1;
        *(__nv_bfloat162*)(olo + (size_t)d * DH + tid * 4)     = l0;
        *(__nv_bfloat162*)(olo + (size_t)d * DH + tid * 4 + 2) = l1;
    } else {
        *(float4*)(out + (size_t)d * DH + tid * 4) = acc;
    }
}

// ---------------- pooling ----------------------------------------------------
__global__ void pool_init_kernel(float* __restrict__ sum, float* __restrict__ mx,
                                 int* __restrict__ cnt) {
    int i = blockIdx.x * blockDim.x + threadIdx.x;
    if (i < Gg * DH) { sum[i] = 0.f; mx[i] = -INFINITY; }
    if (i < Gg) cnt[i] = 0;
}

__global__ void count_kernel(const int* __restrict__ batch, int* __restrict__ cnt) {
    int i = blockIdx.x * blockDim.x + threadIdx.x;
    if (i < Nn) atomicAdd(&cnt[batch[i]], 1);
}

__global__ void pool_accum_kernel(const float* __restrict__ x, const int* __restrict__ batch,
                                  float* __restrict__ gsum, float* __restrict__ gmax) {
    int c  = blockIdx.x * 256 + threadIdx.x;
    int n0 = blockIdx.y * 128;
    int n1 = min(n0 + 128, Nn);
    float sum = 0.f, mx = -INFINITY;
    int cur = batch[n0];
    for (int n = n0; n < n1; ++n) {
        int g = batch[n];
        if (g != cur) {
            atomicAdd(&gsum[cur * DH + c], sum);
            atomicMaxF(&gmax[cur * DH + c], mx);
            sum = 0.f; mx = -INFINITY; cur = g;
        }
        float v = x[(size_t)n * DH + c];
        sum += v; if (v > mx) mx = v;
    }
    atomicAdd(&gsum[cur * DH + c], sum);
    atomicMaxF(&gmax[cur * DH + c], mx);
}

__global__ void pool_final_kernel(const float* __restrict__ gsum, const float* __restrict__ gmax,
                                  const int* __restrict__ cnt, float* __restrict__ pool) {
    int i = blockIdx.x * blockDim.x + threadIdx.x;
    if (i >= Gg * DH) return;
    int g = i >> 10, c = i & (DH - 1);
    float cf = (float)cnt[g]; if (cf < 1.f) cf = 1.f;
    pool[g * 2 * DH + c] = gsum[i] / cf;
    float mv = gmax[i];
    pool[g * 2 * DH + DH + c] = isfinite(mv) ? mv : 0.f;
}

// ---------------- classifier -------------------------------------------------
__global__ void fc_kernel(const float* __restrict__ in, const float* __restrict__ W,
                          const float* __restrict__ b, float* __restrict__ out,
                          int K, int Nout, int dorelu) {
    __shared__ float sh[2048];
    int g = blockIdx.x;
    for (int k = threadIdx.x; k < K; k += blockDim.x) sh[k] = in[g * K + k];
    __syncthreads();
    int j = threadIdx.x;
    float a = b[j];
#pragma unroll 8
    for (int k = 0; k < K; k++) a = fmaf(sh[k], W[(size_t)k * Nout + j], a);
    if (dorelu) a = fmaxf(a, 0.f);
    out[g * Nout + j] = a;
}

__global__ void fc3_kernel(const float* __restrict__ in, const float* __restrict__ W,
                           const float* __restrict__ b, float* __restrict__ out) {
    int t = threadIdx.x;
    if (t >= Gg * 5) return;
    int g = t / 5, j = t % 5;
    float a = b[j];
    for (int k = 0; k < 256; k++) a = fmaf(in[g * 256 + k], W[k * 5 + j], a);
    out[g * 5 + j] = a;
}

// ---------------- host -------------------------------------------------------
extern "C" void kernel_launch(void* const* d_in, const int* in_sizes, int n_in,
                              void* d_out, int out_size) {
    (void)in_sizes; (void)n_in; (void)out_size;
    const float* x   = (const float*)d_in[0];
    const int*   ei  = (const int*)  d_in[1];
    const int*   bat = (const int*)  d_in[2];
    const float* W1  = (const float*)d_in[3];
    const float* as1 = (const float*)d_in[4];
    const float* ad1 = (const float*)d_in[5];
    const float* b1  = (const float*)d_in[6];
    const float* W2  = (const float*)d_in[7];
    const float* as2 = (const float*)d_in[8];
    const float* ad2 = (const float*)d_in[9];
    const float* b2  = (const float*)d_in[10];
    const float* Wc1 = (const float*)d_in[11];
    const float* bc1 = (const float*)d_in[12];
    const float* Wc2 = (const float*)d_in[13];
    const float* bc2 = (const float*)d_in[14];
    const float* Wc3 = (const float*)d_in[15];
    const float* bc3 = (const float*)d_in[16];
    float* out = (float*)d_out;

    float *ph, *px, *pes, *ped, *psum, *pmax, *ppool, *pf1, *pf2;
    int *pcnt, *pdeg, *poff, *pcur, *pcsr;
    __nv_bfloat16 *pwthi, *pwtlo, *pahi, *palo;
    cudaGetSymbolAddress((void**)&ph,   g_h);
    cudaGetSymbolAddress((void**)&px,   g_x);
    cudaGetSymbolAddress((void**)&pes,  g_esrc);
    cudaGetSymbolAddress((void**)&ped,  g_edst);
    cudaGetSymbolAddress((void**)&psum, g_sum);
    cudaGetSymbolAddress((void**)&pmax, g_max);
    cudaGetSymbolAddress((void**)&pcnt, g_cnt);
    cudaGetSymbolAddress((void**)&ppool,g_pool);
    cudaGetSymbolAddress((void**)&pf1,  g_fc1);
    cudaGetSymbolAddress((void**)&pf2,  g_fc2);
    cudaGetSymbolAddress((void**)&pwthi, g_wthi);
    cudaGetSymbolAddress((void**)&pwtlo, g_wtlo);
    cudaGetSymbolAddress((void**)&pahi, g_ahi);
    cudaGetSymbolAddress((void**)&palo, g_alo);
    cudaGetSymbolAddress((void**)&pdeg, g_deg);
    cudaGetSymbolAddress((void**)&poff, g_off);
    cudaGetSymbolAddress((void**)&pcur, g_cur);
    cudaGetSymbolAddress((void**)&pcsr, g_csr);

    cudaFuncSetAttribute(gemm_mma_kernel,
                         cudaFuncAttributeMaxDynamicSharedMemorySize, GEMM_SMEM);

    const int* src = ei;
    const int* dst = ei + Ee;

    const int GRID_E = (EP + 255) / 256;
    const int GRID_N = (Nn + 255) / 256;
    const dim3 gemm_grid(DH / 256, (Nn + 127) / 128);   // (4, 391)

    // ---- CSR build (graph is identical for both layers) ----
    csr_zero_kernel<<<GRID_N, 256>>>(pdeg, pcur);
    csr_hist_kernel<<<GRID_E, 256>>>(dst, pdeg);
    csr_scan_kernel<<<1, 1024>>>(pdeg, poff);
    csr_fill_kernel<<<GRID_E, 256>>>(src, dst, poff, pcur, pcsr);

    // ---- GAT layer 1 ----
    wsplit_kernel<<<(DIN * DH + 255) / 256, 256>>>(W1, pwthi, pwtlo, DIN);
    asplit_kernel<<<(Nn * DIN + 255) / 256, 256>>>(x, pahi, palo, Nn * DIN);
    gemm_mma_kernel<<<gemm_grid, 512, GEMM_SMEM>>>(pahi, palo, pwthi, pwtlo,
                                                   ph, Nn, DIN,
                                                   as1, ad1, pes, ped);
    agg_kernel<<<Nn, 256>>>(poff, pcsr, pes, ped, ph, b1, (float*)0, pahi, palo);

    // ---- GAT layer 2 ----
    wsplit_kernel<<<(DH * DH + 255) / 256, 256>>>(W2, pwthi, pwtlo, DH);
    gemm_mma_kernel<<<gemm_grid, 512, GEMM_SMEM>>>(pahi, palo, pwthi, pwtlo,
                                                   ph, Nn, DH,
                                                   as2, ad2, pes, ped);
    agg_kernel<<<Nn, 256>>>(poff, pcsr, pes, ped, ph, b2, px,
                            (__nv_bfloat16*)0, (__nv_bfloat16*)0);

    // ---- pooling ----
    pool_init_kernel<<<(Gg * DH + 255) / 256, 256>>>(psum, pmax, pcnt);
    count_kernel<<<GRID_N, 256>>>(bat, pcnt);
    pool_accum_kernel<<<dim3(DH / 256, (Nn + 127) / 128), 256>>>(px, bat, psum, pmax);
    pool_final_kernel<<<(Gg * DH + 255) / 256, 256>>>(psum, pmax, pcnt, ppool);

    // ---- classifier ----
    fc_kernel<<<Gg, 512>>>(ppool, Wc1, bc1, pf1, 2 * DH, 512, 1);
    fc_kernel<<<Gg, 256>>>(pf1, Wc2, bc2, pf2, 512, 256, 1);
    fc3_kernel<<<1, Gg * 5>>>(pf2, Wc3, bc3, out);
}

// round 15
// speedup vs baseline: 1.0370x; 1.0370x over previous
#include <cuda_runtime.h>
#include <cuda_bf16.h>
#include <math.h>
#include <stdint.h>

#define Nn   50000
#define Ee   200000
#define EP   (Ee + Nn)      // 250000 edges incl. self loops
#define Gg   64
#define Hh   4
#define Cch  256
#define DH   1024
#define DIN  768

// ---------------- scratch (device globals; no allocation allowed) ----------
__device__ float g_h  [(size_t)Nn * DH];   // x @ W  (current layer)
__device__ float g_x  [(size_t)Nn * DH];   // layer-2 output (post ELU)
__device__ float g_esrc[Nn * Hh];
__device__ float g_edst[Nn * Hh];
__device__ float g_sum [Gg * DH];
__device__ float g_max [Gg * DH];
__device__ int   g_cnt [Gg];
// transposed + hi/lo split weights: Wt[n][k]
__device__ __nv_bfloat16 g_wthi[(size_t)DH * DH];
__device__ __nv_bfloat16 g_wtlo[(size_t)DH * DH];
// hi/lo split activations (GEMM A operand)
__device__ __nv_bfloat16 g_ahi[(size_t)Nn * DH];
__device__ __nv_bfloat16 g_alo[(size_t)Nn * DH];
// CSR by destination
__device__ int g_deg[Nn];
__device__ int g_off[Nn + 1];
__device__ int g_cur[Nn];
__device__ int g_csr[EP];          // src node per slot

// ---------------- helpers ---------------------------------------------------
__device__ __forceinline__ float lrelu(float x) { return x > 0.f ? x : 0.2f * x; }
__device__ __forceinline__ float eluf (float x) { return x > 0.f ? x : expm1f(x); }

__device__ __forceinline__ void atomicMaxF(float* a, float v) {
    if (v >= 0.f) atomicMax((int*)a, __float_as_int(v));
    else          atomicMin((unsigned int*)a, __float_as_uint(v));
}

__device__ __forceinline__ uint32_t smem_u32(const void* p) {
    uint32_t a;
    asm("{ .reg .u64 t; cvta.to.shared.u64 t, %1; cvt.u32.u64 %0, t; }"
        : "=r"(a) : "l"(p));
    return a;
}

__device__ __forceinline__ void ldm4(uint32_t* r, uint32_t addr) {
    asm volatile("ldmatrix.sync.aligned.m8n8.x4.shared.b16 {%0,%1,%2,%3}, [%4];"
                 : "=r"(r[0]), "=r"(r[1]), "=r"(r[2]), "=r"(r[3]) : "r"(addr));
}

__device__ __forceinline__ void mma16816(float* c, const uint32_t* a,
                                         uint32_t b0, uint32_t b1) {
    asm volatile(
        "mma.sync.aligned.m16n8k16.row.col.f32.bf16.bf16.f32 "
        "{%0,%1,%2,%3}, {%4,%5,%6,%7}, {%8,%9}, {%0,%1,%2,%3};"
        : "+f"(c[0]), "+f"(c[1]), "+f"(c[2]), "+f"(c[3])
        : "r"(a[0]), "r"(a[1]), "r"(a[2]), "r"(a[3]), "r"(b0), "r"(b1));
}

#define CPA16(dst, src) \
    asm volatile("cp.async.cg.shared.global [%0], [%1], 16;" \
                 :: "r"(dst), "l"(src) : "memory")
#define CPA16Z(dst, src, szr) \
    asm volatile("cp.async.cg.shared.global [%0], [%1], 16, %2;" \
                 :: "r"(dst), "l"(src), "r"(szr) : "memory")

// ---------------- CSR build (+ pooling init folded in) -----------------------
#define INIT_TOT (Gg * DH)          // 65536 >= Nn
__global__ void csr_zero_kernel(int* __restrict__ deg, int* __restrict__ cur,
                                float* __restrict__ gsum, float* __restrict__ gmax,
                                int* __restrict__ cnt) {
    int i = blockIdx.x * 256 + threadIdx.x;
    if (i < Nn) { deg[i] = 0; cur[i] = 0; }
    if (i < INIT_TOT) { gsum[i] = 0.f; gmax[i] = -INFINITY; }
    if (i < Gg) cnt[i] = 0;
}

__global__ void csr_hist_kernel(const int* __restrict__ dst, int* __restrict__ deg,
                                const int* __restrict__ batch, int* __restrict__ cnt) {
    int i = blockIdx.x * 256 + threadIdx.x;
    if (i < Nn) atomicAdd(&cnt[batch[i]], 1);
    if (i >= EP) return;
    int d_ = (i < Ee) ? dst[i] : (i - Ee);
    atomicAdd(&deg[d_], 1);
}

__global__ void csr_scan_kernel(const int* __restrict__ deg, int* __restrict__ off) {
    __shared__ int bs[1024];
    const int t = threadIdx.x;
    const int per = (Nn + 1023) / 1024;        // 49
    const int b0 = t * per;
    int loc = 0;
    for (int i = 0; i < per; i++) {
        int idx = b0 + i;
        if (idx < Nn) loc += deg[idx];
    }
    bs[t] = loc;
    __syncthreads();
    for (int o = 1; o < 1024; o <<= 1) {
        int v = (t >= o) ? bs[t - o] : 0;
        __syncthreads();
        bs[t] += v;
        __syncthreads();
    }
    int run = t ? bs[t - 1] : 0;
    for (int i = 0; i < per; i++) {
        int idx = b0 + i;
        if (idx < Nn) { off[idx] = run; run += deg[idx]; }
    }
    if (t == 1023) off[Nn] = run;
}

__global__ void csr_fill_kernel(const int* __restrict__ src, const int* __restrict__ dst,
                                const int* __restrict__ off, int* __restrict__ cur,
                                int* __restrict__ csr) {
    int i = blockIdx.x * 256 + threadIdx.x;
    if (i >= EP) return;
    int s_, d_;
    if (i < Ee) { s_ = src[i]; d_ = dst[i]; } else { s_ = d_ = i - Ee; }
    int pos = off[d_] + atomicAdd(&cur[d_], 1);
    csr[pos] = s_;
}

// ---------------- splits -----------------------------------------------------
__global__ void wsplit_kernel(const float* __restrict__ W,
                              __nv_bfloat16* __restrict__ hi,
                              __nv_bfloat16* __restrict__ lo, int K) {
    int idx = blockIdx.x * 256 + threadIdx.x;
    if (idx >= K * DH) return;
    int n = idx & (DH - 1), k = idx >> 10;   // W[k][n], row-major (K, 1024)
    float v = W[idx];
    __nv_bfloat16 h = __float2bfloat16(v);
    hi[(size_t)n * K + k] = h;
    lo[(size_t)n * K + k] = __float2bfloat16(v - __bfloat162float(h));
}

__global__ void asplit_kernel(const float* __restrict__ A,
                              __nv_bfloat16* __restrict__ hi,
                              __nv_bfloat16* __restrict__ lo, int total) {
    int idx = blockIdx.x * 256 + threadIdx.x;
    if (idx >= total) return;
    float v = A[idx];
    __nv_bfloat16 h = __float2bfloat16(v);
    hi[idx] = h;
    lo[idx] = __float2bfloat16(v - __bfloat162float(h));
}

// ---------------- tensor-core GEMM via mma.sync (bf16x3 split) --------------
// C[M,1024] = A[M,K] @ W[K,1024]; fused attention-score epilogue:
// col tile == one head (N-tile 256), so this CTA computes es/ed for its rows.
#define GEMM_SMEM (2 * 98304)

__global__ __launch_bounds__(512, 1)
void gemm_mma_kernel(const __nv_bfloat16* __restrict__ Ahi,
                     const __nv_bfloat16* __restrict__ Alo,
                     const __nv_bfloat16* __restrict__ Bhi,
                     const __nv_bfloat16* __restrict__ Blo,
                     float* __restrict__ C, int M, int K,
                     const float* __restrict__ asrc,
                     const float* __restrict__ adst,
                     float* __restrict__ es, float* __restrict__ ed) {
    extern __shared__ __align__(1024) char smem[];
    const int tid = threadIdx.x, wid = tid >> 5, lane = tid & 31;
    const int wm = wid & 3, wn = wid >> 2;
    const int lr = lane & 15, lh = lane >> 4;
    const int row0 = blockIdx.y * 128, col0 = blockIdx.x * 256;
    const int head = blockIdx.x;               // 256-wide col tile == head
    const uint32_t sb = smem_u32(smem);
    const int nc = K >> 6;

    float acc[2][8][4];
#pragma unroll
    for (int t = 0; t < 2; t++)
#pragma unroll
        for (int j = 0; j < 8; j++)
#pragma unroll
            for (int q = 0; q < 4; q++) acc[t][j][q] = 0.f;

    auto loadStage = [&](int ck) {
        uint32_t st = sb + (uint32_t)(ck & 1) * 98304u;
        const __nv_bfloat16* Ah = Ahi + (size_t)row0 * K + ck * 64;
        const __nv_bfloat16* Al = Alo + (size_t)row0 * K + ck * 64;
#pragma unroll
        for (int u = tid; u < 1024; u += 512) {
            int r = u >> 3, c = u & 7;
            uint32_t d = st + (uint32_t)(r * 128) + (uint32_t)((c ^ (r & 7)) << 4);
            uint32_t sz = (row0 + r < M) ? 16u : 0u;
            CPA16Z(d,          Ah + (size_t)r * K + c * 8, sz);
            CPA16Z(d + 16384u, Al + (size_t)r * K + c * 8, sz);
        }
        const __nv_bfloat16* Bh = Bhi + (size_t)col0 * K + ck * 64;
        const __nv_bfloat16* Bl = Blo + (size_t)col0 * K + ck * 64;
#pragma unroll
        for (int u = tid; u < 2048; u += 512) {
            int r = u >> 3, c = u & 7;
            uint32_t d = st + 32768u + (uint32_t)(r * 128) +
                         (uint32_t)((c ^ (r & 7)) << 4);
            CPA16(d,          Bh + (size_t)r * K + c * 8);
            CPA16(d + 32768u, Bl + (size_t)r * K + c * 8);
        }
        asm volatile("cp.async.commit_group;" ::: "memory");
    };

    auto compute = [&](int ck) {
        uint32_t base = sb + (uint32_t)(ck & 1) * 98304u;
#pragma unroll
        for (int ks = 0; ks < 4; ks++) {
            uint32_t c16 = (uint32_t)(ks * 2 + lh);
            uint32_t ah[2][4], al[2][4];
#pragma unroll
            for (int t = 0; t < 2; t++) {
                int row = wm * 32 + t * 16 + lr;
                uint32_t ad = base + (uint32_t)(row * 128) +
                              ((c16 ^ (uint32_t)(row & 7)) << 4);
                ldm4(ah[t], ad);
                ldm4(al[t], ad + 16384u);
            }
#pragma unroll
            for (int g = 0; g < 4; g++) {
                int row = wn * 64 + g * 16 + lr;
                uint32_t bd = base + 32768u + (uint32_t)(row * 128) +
                              ((c16 ^ (uint32_t)(row & 7)) << 4);
                uint32_t bh[4], bl[4];
                ldm4(bh, bd);
                ldm4(bl, bd + 32768u);
#pragma unroll
                for (int t = 0; t < 2; t++)
#pragma unroll
                    for (int o = 0; o < 2; o++) {
                        float* a4 = acc[t][g * 2 + o];
                        mma16816(a4, ah[t], bh[o], bh[o + 2]);   // hi*hi
                        mma16816(a4, al[t], bh[o], bh[o + 2]);   // lo*hi
                        mma16816(a4, ah[t], bl[o], bl[o + 2]);   // hi*lo
                    }
            }
        }
    };

    // ---- prologue ----
    loadStage(0);
    if (nc > 1) loadStage(1);
    asm volatile("cp.async.wait_group %0;" :: "n"(1) : "memory");
    __syncthreads();

    // ---- mainloop ----
    for (int c = 0; c < nc; ++c) {
        compute(c);
        __syncthreads();
        if (c + 1 < nc) {
            if (c + 2 < nc) {
                loadStage(c + 2);
                asm volatile("cp.async.wait_group %0;" :: "n"(1) : "memory");
            } else {
                asm volatile("cp.async.wait_group %0;" :: "n"(0) : "memory");
            }
            __syncthreads();
        }
    }

    // ---- epilogue: C store + fused per-head attention scores ----
    float* sred = (float*)smem;                 // [0:128) src, [128:256) dst
#pragma unroll
    for (int i = tid; i < 256; i += 512) sred[i] = 0.f;

    float psum[2][2] = {{0.f, 0.f}, {0.f, 0.f}};
    float pdum[2][2] = {{0.f, 0.f}, {0.f, 0.f}};
#pragma unroll
    for (int t = 0; t < 2; t++) {
        int m0 = row0 + wm * 32 + t * 16 + (lane >> 2);
#pragma unroll
        for (int j = 0; j < 8; j++) {
            int cloc = wn * 64 + j * 8 + (lane & 3) * 2;
            int col = col0 + cloc;
            if (m0 < M)
                *(float2*)(C + (size_t)m0 * DH + col) =
                    make_float2(acc[t][j][0], acc[t][j][1]);
            if (m0 + 8 < M)
                *(float2*)(C + (size_t)(m0 + 8) * DH + col) =
                    make_float2(acc[t][j][2], acc[t][j][3]);
            float a0 = asrc[head * Cch + cloc], a1 = asrc[head * Cch + cloc + 1];
            float d0 = adst[head * Cch + cloc], d1 = adst[head * Cch + cloc + 1];
            psum[t][0] += acc[t][j][0] * a0 + acc[t][j][1] * a1;
            psum[t][1] += acc[t][j][2] * a0 + acc[t][j][3] * a1;
            pdum[t][0] += acc[t][j][0] * d0 + acc[t][j][1] * d1;
            pdum[t][1] += acc[t][j][2] * d0 + acc[t][j][3] * d1;
        }
    }
    // reduce over the 4 lanes of each quad (lane&3)
#pragma unroll
    for (int t = 0; t < 2; t++)
#pragma unroll
        for (int r2 = 0; r2 < 2; r2++) {
            psum[t][r2] += __shfl_xor_sync(0xffffffffu, psum[t][r2], 1);
            psum[t][r2] += __shfl_xor_sync(0xffffffffu, psum[t][r2], 2);
            pdum[t][r2] += __shfl_xor_sync(0xffffffffu, pdum[t][r2], 1);
            pdum[t][r2] += __shfl_xor_sync(0xffffffffu, pdum[t][r2], 2);
        }
    __syncthreads();            // sred zero-fill visible; stage reads long done
    if ((lane & 3) == 0) {
#pragma unroll
        for (int t = 0; t < 2; t++)
#pragma unroll
            for (int r2 = 0; r2 < 2; r2++) {
                int rl = wm * 32 + t * 16 + r2 * 8 + (lane >> 2);
                atomicAdd(&sred[rl],       psum[t][r2]);
                atomicAdd(&sred[128 + rl], pdum[t][r2]);
            }
    }
    __syncthreads();
#pragma unroll
    for (int r2 = tid; r2 < 128; r2 += 512) {
        int n = row0 + r2;
        if (n < M) {
            es[n * Hh + head] = sred[r2];
            ed[n * Hh + head] = sred[128 + r2];
        }
    }
}

// ---------------- fused softmax + gather aggregation (R12 form) --------------
__global__ __launch_bounds__(256)
void agg_kernel(const int* __restrict__ off, const int* __restrict__ csr,
                const float* __restrict__ es, const float* __restrict__ ed,
                const float* __restrict__ h, const float* __restrict__ bias,
                float* __restrict__ out,
                __nv_bfloat16* __restrict__ ohi, __nv_bfloat16* __restrict__ olo) {
    const int d = blockIdx.x;
    const int beg = off[d], end = off[d + 1];
    const int deg = end - beg;
    const int tid = threadIdx.x, wid = tid >> 5, lane = tid & 31;

    __shared__ float sm[4], ss[4];
    __shared__ float al[4][64];

    if (wid < 4) {
        const float edv = ed[d * 4 + wid];
        float mx = -INFINITY;
        for (int i = beg + lane; i < end; i += 32) {
            int s_ = csr[i];
            mx = fmaxf(mx, lrelu(es[s_ * 4 + wid] + edv));
        }
#pragma unroll
        for (int o = 16; o; o >>= 1)
            mx = fmaxf(mx, __shfl_xor_sync(0xffffffffu, mx, o));
        float su = 0.f;
        for (int i = beg + lane; i < end; i += 32) {
            int s_ = csr[i];
            su += expf(lrelu(es[s_ * 4 + wid] + edv) - mx);
        }
#pragma unroll
        for (int o = 16; o; o >>= 1)
            su += __shfl_xor_sync(0xffffffffu, su, o);
        if (lane == 0) { sm[wid] = mx; ss[wid] = su; }
    }
    __syncthreads();

    const int head = tid >> 6;
    float4 acc = make_float4(0.f, 0.f, 0.f, 0.f);

    for (int c0 = 0; c0 < deg; c0 += 64) {
        {
            int j = tid & 63, hh = tid >> 6;
            if (c0 + j < deg) {
                int s_ = csr[beg + c0 + j];
                float e = lrelu(es[s_ * 4 + hh] + ed[d * 4 + hh]);
                al[hh][j] = expf(e - sm[hh]) / (ss[hh] + 1e-16f);
            }
        }
        __syncthreads();
        int lim = min(64, deg - c0);
        for (int j = 0; j < lim; j++) {
            int s_ = csr[beg + c0 + j];
            float a = al[head][j];
            float4 v = *(const float4*)(h + (size_t)s_ * DH + tid * 4);
            acc.x = fmaf(a, v.x, acc.x);
            acc.y = fmaf(a, v.y, acc.y);
            acc.z = fmaf(a, v.z, acc.z);
            acc.w = fmaf(a, v.w, acc.w);
        }
        __syncthreads();
    }

    float4 bb = *(const float4*)(bias + tid * 4);
    acc.x = eluf(acc.x + bb.x);
    acc.y = eluf(acc.y + bb.y);
    acc.z = eluf(acc.z + bb.z);
    acc.w = eluf(acc.w + bb.w);

    if (ohi) {
        __nv_bfloat162 h0 = __floats2bfloat162_rn(acc.x, acc.y);
        __nv_bfloat162 h1 = __floats2bfloat162_rn(acc.z, acc.w);
        __nv_bfloat162 l0 = __floats2bfloat162_rn(acc.x - __bfloat162float(h0.x),
                                                  acc.y - __bfloat162float(h0.y));
        __nv_bfloat162 l1 = __floats2bfloat162_rn(acc.z - __bfloat162float(h1.x),
                                                  acc.w - __bfloat162float(h1.y));
        *(__nv_bfloat162*)(ohi + (size_t)d * DH + tid * 4)     = h0;
        *(__nv_bfloat162*)(ohi + (size_t)d * DH + tid * 4 + 2) = h1;
        *(__nv_bfloat162*)(olo + (size_t)d * DH + tid * 4)     = l0;
        *(__nv_bfloat162*)(olo + (size_t)d * DH + tid * 4 + 2) = l1;
    } else {
        *(float4*)(out + (size_t)d * DH + tid * 4) = acc;
    }
}

// ---------------- pooling accumulate (run-length over sorted batch) ----------
__global__ void pool_accum_kernel(const float* __restrict__ x, const int* __restrict__ batch,
                                  float* __restrict__ gsum, float* __restrict__ gmax) {
    int c  = blockIdx.x * 256 + threadIdx.x;
    int n0 = blockIdx.y * 128;
    int n1 = min(n0 + 128, Nn);
    float sum = 0.f, mx = -INFINITY;
    int cur = batch[n0];
    for (int n = n0; n < n1; ++n) {
        int g = batch[n];
        if (g != cur) {
            atomicAdd(&gsum[cur * DH + c], sum);
            atomicMaxF(&gmax[cur * DH + c], mx);
            sum = 0.f; mx = -INFINITY; cur = g;
        }
        float v = x[(size_t)n * DH + c];
        sum += v; if (v > mx) mx = v;
    }
    atomicAdd(&gsum[cur * DH + c], sum);
    atomicMaxF(&gmax[cur * DH + c], mx);
}

// ---------------- fused classifier: pool_final + fc1 + fc2 + fc3 -------------
// one block per graph; whole MLP chain in shared memory.
__global__ __launch_bounds__(512)
void classifier_kernel(const float* __restrict__ gsum, const float* __restrict__ gmax,
                       const int* __restrict__ cnt,
                       const float* __restrict__ Wc1, const float* __restrict__ bc1,
                       const float* __restrict__ Wc2, const float* __restrict__ bc2,
                       const float* __restrict__ Wc3, const float* __restrict__ bc3,
                       float* __restrict__ out) {
    __shared__ float pool[2 * DH];
    __shared__ float f1[512];
    __shared__ float f2[256];
    const int g = blockIdx.x, tid = threadIdx.x;

    float cf = (float)cnt[g]; if (cf < 1.f) cf = 1.f;
    for (int c = tid; c < DH; c += 512) {
        pool[c] = gsum[g * DH + c] / cf;
        float mv = gmax[g * DH + c];
        pool[DH + c] = isfinite(mv) ? mv : 0.f;
    }
    __syncthreads();

    {   // fc1: 2048 -> 512, relu
        float a = bc1[tid];
#pragma unroll 8
        for (int k = 0; k < 2 * DH; k++)
            a = fmaf(pool[k], Wc1[(size_t)k * 512 + tid], a);
        f1[tid] = fmaxf(a, 0.f);
    }
    __syncthreads();

    if (tid < 256) {   // fc2: 512 -> 256, relu
        float a = bc2[tid];
#pragma unroll 8
        for (int k = 0; k < 512; k++)
            a = fmaf(f1[k], Wc2[(size_t)k * 256 + tid], a);
        f2[tid] = fmaxf(a, 0.f);
    }
    __syncthreads();

    if (tid < 5) {     // fc3: 256 -> 5
        float a = bc3[tid];
        for (int k = 0; k < 256; k++)
            a = fmaf(f2[k], Wc3[k * 5 + tid], a);
        out[g * 5 + tid] = a;
    }
}

// ---------------- host -------------------------------------------------------
extern "C" void kernel_launch(void* const* d_in, const int* in_sizes, int n_in,
                              void* d_out, int out_size) {
    (void)in_sizes; (void)n_in; (void)out_size;
    const float* x   = (const float*)d_in[0];
    const int*   ei  = (const int*)  d_in[1];
    const int*   bat = (const int*)  d_in[2];
    const float* W1  = (const float*)d_in[3];
    const float* as1 = (const float*)d_in[4];
    const float* ad1 = (const float*)d_in[5];
    const float* b1  = (const float*)d_in[6];
    const float* W2  = (const float*)d_in[7];
    const float* as2 = (const float*)d_in[8];
    const float* ad2 = (const float*)d_in[9];
    const float* b2  = (const float*)d_in[10];
    const float* Wc1 = (const float*)d_in[11];
    const float* bc1 = (const float*)d_in[12];
    const float* Wc2 = (const float*)d_in[13];
    const float* bc2 = (const float*)d_in[14];
    const float* Wc3 = (const float*)d_in[15];
    const float* bc3 = (const float*)d_in[16];
    float* out = (float*)d_out;

    float *ph, *px, *pes, *ped, *psum, *pmax;
    int *pcnt, *pdeg, *poff, *pcur, *pcsr;
    __nv_bfloat16 *pwthi, *pwtlo, *pahi, *palo;
    cudaGetSymbolAddress((void**)&ph,   g_h);
    cudaGetSymbolAddress((void**)&px,   g_x);
    cudaGetSymbolAddress((void**)&pes,  g_esrc);
    cudaGetSymbolAddress((void**)&ped,  g_edst);
    cudaGetSymbolAddress((void**)&psum, g_sum);
    cudaGetSymbolAddress((void**)&pmax, g_max);
    cudaGetSymbolAddress((void**)&pcnt, g_cnt);
    cudaGetSymbolAddress((void**)&pwthi, g_wthi);
    cudaGetSymbolAddress((void**)&pwtlo, g_wtlo);
    cudaGetSymbolAddress((void**)&pahi, g_ahi);
    cudaGetSymbolAddress((void**)&palo, g_alo);
    cudaGetSymbolAddress((void**)&pdeg, g_deg);
    cudaGetSymbolAddress((void**)&poff, g_off);
    cudaGetSymbolAddress((void**)&pcur, g_cur);
    cudaGetSymbolAddress((void**)&pcsr, g_csr);

    cudaFuncSetAttribute(gemm_mma_kernel,
                         cudaFuncAttributeMaxDynamicSharedMemorySize, GEMM_SMEM);

    const int* src = ei;
    const int* dst = ei + Ee;

    const int GRID_E = (EP + 255) / 256;
    const int GRID_I = (INIT_TOT + 255) / 256;
    const dim3 gemm_grid(DH / 256, (Nn + 127) / 128);   // (4, 391)

    // ---- CSR build + pooling init (graph is identical for both layers) ----
    csr_zero_kernel<<<GRID_I, 256>>>(pdeg, pcur, psum, pmax, pcnt);
    csr_hist_kernel<<<GRID_E, 256>>>(dst, pdeg, bat, pcnt);
    csr_scan_kernel<<<1, 1024>>>(pdeg, poff);
    csr_fill_kernel<<<GRID_E, 256>>>(src, dst, poff, pcur, pcsr);

    // ---- GAT layer 1 ----
    wsplit_kernel<<<(DIN * DH + 255) / 256, 256>>>(W1, pwthi, pwtlo, DIN);
    asplit_kernel<<<(Nn * DIN + 255) / 256, 256>>>(x, pahi, palo, Nn * DIN);
    gemm_mma_kernel<<<gemm_grid, 512, GEMM_SMEM>>>(pahi, palo, pwthi, pwtlo,
                                                   ph, Nn, DIN,
                                                   as1, ad1, pes, ped);
    agg_kernel<<<Nn, 256>>>(poff, pcsr, pes, ped, ph, b1, (float*)0, pahi, palo);

    // ---- GAT layer 2 ----
    wsplit_kernel<<<(DH * DH + 255) / 256, 256>>>(W2, pwthi, pwtlo, DH);
    gemm_mma_kernel<<<gemm_grid, 512, GEMM_SMEM>>>(pahi, palo, pwthi, pwtlo,
                                                   ph, Nn, DH,
                                                   as2, ad2, pes, ped);
    agg_kernel<<<Nn, 256>>>(poff, pcsr, pes, ped, ph, b2, px,
                            (__nv_bfloat16*)0, (__nv_bfloat16*)0);

    // ---- pooling + classifier ----
    pool_accum_kernel<<<dim3(DH / 256, (Nn + 127) / 128), 256>>>(px, bat, psum, pmax);
    classifier_kernel<<<Gg, 512>>>(psum, pmax, pcnt,
                                   Wc1, bc1, Wc2, bc2, Wc3, bc3, out);
}

// round 16
// speedup vs baseline: 1.2386x; 1.1944x over previous
#include <cuda_runtime.h>
#include <cuda_fp16.h>
#include <math.h>
#include <stdint.h>

#define Nn   50000
#define Ee   200000
#define EP   (Ee + Nn)      // 250000 edges incl. self loops
#define Gg   64
#define Hh   4
#define Cch  256
#define DH   1024
#define DIN  768

// ---------------- scratch (device globals; no allocation allowed) ----------
__device__ float g_h  [(size_t)Nn * DH];   // x @ W  (current layer)
__device__ float g_x  [(size_t)Nn * DH];   // layer-2 output (post ELU)
__device__ float g_esrc[Nn * Hh];
__device__ float g_edst[Nn * Hh];
__device__ float g_sum [Gg * DH];
__device__ float g_max [Gg * DH];
__device__ int   g_cnt [Gg];
// transposed fp16 weights: Wt[n][k]  (single rounded copy)
__device__ __half g_wth[(size_t)DH * DH];
// hi/lo fp16 split activations (GEMM A operand)
__device__ __half g_ahi[(size_t)Nn * DH];
__device__ __half g_alo[(size_t)Nn * DH];
// CSR by destination
__device__ int g_deg[Nn];
__device__ int g_off[Nn + 1];
__device__ int g_cur[Nn];
__device__ int g_csr[EP];          // src node per slot

// ---------------- helpers ---------------------------------------------------
__device__ __forceinline__ float lrelu(float x) { return x > 0.f ? x : 0.2f * x; }
__device__ __forceinline__ float eluf (float x) { return x > 0.f ? x : expm1f(x); }

__device__ __forceinline__ void atomicMaxF(float* a, float v) {
    if (v >= 0.f) atomicMax((int*)a, __float_as_int(v));
    else          atomicMin((unsigned int*)a, __float_as_uint(v));
}

__device__ __forceinline__ uint32_t smem_u32(const void* p) {
    uint32_t a;
    asm("{ .reg .u64 t; cvta.to.shared.u64 t, %1; cvt.u32.u64 %0, t; }"
        : "=r"(a) : "l"(p));
    return a;
}

__device__ __forceinline__ void ldm4(uint32_t* r, uint32_t addr) {
    asm volatile("ldmatrix.sync.aligned.m8n8.x4.shared.b16 {%0,%1,%2,%3}, [%4];"
                 : "=r"(r[0]), "=r"(r[1]), "=r"(r[2]), "=r"(r[3]) : "r"(addr));
}

__device__ __forceinline__ void mma16816(float* c, const uint32_t* a,
                                         uint32_t b0, uint32_t b1) {
    asm volatile(
        "mma.sync.aligned.m16n8k16.row.col.f32.f16.f16.f32 "
        "{%0,%1,%2,%3}, {%4,%5,%6,%7}, {%8,%9}, {%0,%1,%2,%3};"
        : "+f"(c[0]), "+f"(c[1]), "+f"(c[2]), "+f"(c[3])
        : "r"(a[0]), "r"(a[1]), "r"(a[2]), "r"(a[3]), "r"(b0), "r"(b1));
}

#define CPA16(dst, src) \
    asm volatile("cp.async.cg.shared.global [%0], [%1], 16;" \
                 :: "r"(dst), "l"(src) : "memory")
#define CPA16Z(dst, src, szr) \
    asm volatile("cp.async.cg.shared.global [%0], [%1], 16, %2;" \
                 :: "r"(dst), "l"(src), "r"(szr) : "memory")

// ---------------- CSR build (+ pooling init folded in) -----------------------
#define INIT_TOT (Gg * DH)          // 65536 >= Nn
__global__ void csr_zero_kernel(int* __restrict__ deg, int* __restrict__ cur,
                                float* __restrict__ gsum, float* __restrict__ gmax,
                                int* __restrict__ cnt) {
    int i = blockIdx.x * 256 + threadIdx.x;
    if (i < Nn) { deg[i] = 0; cur[i] = 0; }
    if (i < INIT_TOT) { gsum[i] = 0.f; gmax[i] = -INFINITY; }
    if (i < Gg) cnt[i] = 0;
}

__global__ void csr_hist_kernel(const int* __restrict__ dst, int* __restrict__ deg,
                                const int* __restrict__ batch, int* __restrict__ cnt) {
    int i = blockIdx.x * 256 + threadIdx.x;
    if (i < Nn) atomicAdd(&cnt[batch[i]], 1);
    if (i >= EP) return;
    int d_ = (i < Ee) ? dst[i] : (i - Ee);
    atomicAdd(&deg[d_], 1);
}

__global__ void csr_scan_kernel(const int* __restrict__ deg, int* __restrict__ off) {
    __shared__ int bs[1024];
    const int t = threadIdx.x;
    const int per = (Nn + 1023) / 1024;        // 49
    const int b0 = t * per;
    int loc = 0;
    for (int i = 0; i < per; i++) {
        int idx = b0 + i;
        if (idx < Nn) loc += deg[idx];
    }
    bs[t] = loc;
    __syncthreads();
    for (int o = 1; o < 1024; o <<= 1) {
        int v = (t >= o) ? bs[t - o] : 0;
        __syncthreads();
        bs[t] += v;
        __syncthreads();
    }
    int run = t ? bs[t - 1] : 0;
    for (int i = 0; i < per; i++) {
        int idx = b0 + i;
        if (idx < Nn) { off[idx] = run; run += deg[idx]; }
    }
    if (t == 1023) off[Nn] = run;
}

__global__ void csr_fill_kernel(const int* __restrict__ src, const int* __restrict__ dst,
                                const int* __restrict__ off, int* __restrict__ cur,
                                int* __restrict__ csr) {
    int i = blockIdx.x * 256 + threadIdx.x;
    if (i >= EP) return;
    int s_, d_;
    if (i < Ee) { s_ = src[i]; d_ = dst[i]; } else { s_ = d_ = i - Ee; }
    int pos = off[d_] + atomicAdd(&cur[d_], 1);
    csr[pos] = s_;
}

// ---------------- splits -----------------------------------------------------
__global__ void wsplit_kernel(const float* __restrict__ W,
                              __half* __restrict__ hi, int K) {
    int idx = blockIdx.x * 256 + threadIdx.x;
    if (idx >= K * DH) return;
    int n = idx & (DH - 1), k = idx >> 10;   // W[k][n], row-major (K, 1024)
    hi[(size_t)n * K + k] = __float2half_rn(W[idx]);
}

__global__ void asplit_kernel(const float* __restrict__ A,
                              __half* __restrict__ hi,
                              __half* __restrict__ lo, int total) {
    int idx = blockIdx.x * 256 + threadIdx.x;
    if (idx >= total) return;
    float v = A[idx];
    __half h = __float2half_rn(v);
    hi[idx] = h;
    lo[idx] = __float2half_rn(v - __half2float(h));
}

// ---------------- tensor-core GEMM via mma.sync (fp16 x2 split) -------------
// C[M,1024] = A[M,K] @ W[K,1024]; A split hi/lo fp16 (exact to ~2^-22),
// W rounded once to fp16 (error = x·wl ~ 2^-12 relative, inside 1e-3 gate).
// Tile 128x256, 512 threads, K-chunk 64, 2-stage cp.async, fused score epi.
// stage (64KB): Ahi[16K] Alo[16K] Bh[32K]; 128B SW128 rows.
#define GEMM_SMEM (2 * 65536)

__global__ __launch_bounds__(512, 1)
void gemm_mma_kernel(const __half* __restrict__ Ahi,
                     const __half* __restrict__ Alo,
                     const __half* __restrict__ Bh_,
                     float* __restrict__ C, int M, int K,
                     const float* __restrict__ asrc,
                     const float* __restrict__ adst,
                     float* __restrict__ es, float* __restrict__ ed) {
    extern __shared__ __align__(1024) char smem[];
    const int tid = threadIdx.x, wid = tid >> 5, lane = tid & 31;
    const int wm = wid & 3, wn = wid >> 2;
    const int lr = lane & 15, lh = lane >> 4;
    const int row0 = blockIdx.y * 128, col0 = blockIdx.x * 256;
    const int head = blockIdx.x;               // 256-wide col tile == head
    const uint32_t sb = smem_u32(smem);
    const int nc = K >> 6;

    float acc[2][8][4];
#pragma unroll
    for (int t = 0; t < 2; t++)
#pragma unroll
        for (int j = 0; j < 8; j++)
#pragma unroll
            for (int q = 0; q < 4; q++) acc[t][j][q] = 0.f;

    auto loadStage = [&](int ck) {
        uint32_t st = sb + (uint32_t)(ck & 1) * 65536u;
        const __half* Ah = Ahi + (size_t)row0 * K + ck * 64;
        const __half* Al = Alo + (size_t)row0 * K + ck * 64;
#pragma unroll
        for (int u = tid; u < 1024; u += 512) {
            int r = u >> 3, c = u & 7;
            uint32_t d = st + (uint32_t)(r * 128) + (uint32_t)((c ^ (r & 7)) << 4);
            uint32_t sz = (row0 + r < M) ? 16u : 0u;
            CPA16Z(d,          Ah + (size_t)r * K + c * 8, sz);
            CPA16Z(d + 16384u, Al + (size_t)r * K + c * 8, sz);
        }
        const __half* Bp = Bh_ + (size_t)col0 * K + ck * 64;
#pragma unroll
        for (int u = tid; u < 2048; u += 512) {
            int r = u >> 3, c = u & 7;
            uint32_t d = st + 32768u + (uint32_t)(r * 128) +
                         (uint32_t)((c ^ (r & 7)) << 4);
            CPA16(d, Bp + (size_t)r * K + c * 8);
        }
        asm volatile("cp.async.commit_group;" ::: "memory");
    };

    auto compute = [&](int ck) {
        uint32_t base = sb + (uint32_t)(ck & 1) * 65536u;
#pragma unroll
        for (int ks = 0; ks < 4; ks++) {
            uint32_t c16 = (uint32_t)(ks * 2 + lh);
            uint32_t ah[2][4], al[2][4];
#pragma unroll
            for (int t = 0; t < 2; t++) {
                int row = wm * 32 + t * 16 + lr;
                uint32_t ad = base + (uint32_t)(row * 128) +
                              ((c16 ^ (uint32_t)(row & 7)) << 4);
                ldm4(ah[t], ad);
                ldm4(al[t], ad + 16384u);
            }
#pragma unroll
            for (int g = 0; g < 4; g++) {
                int row = wn * 64 + g * 16 + lr;
                uint32_t bd = base + 32768u + (uint32_t)(row * 128) +
                              ((c16 ^ (uint32_t)(row & 7)) << 4);
                uint32_t bh[4];
                ldm4(bh, bd);
#pragma unroll
                for (int t = 0; t < 2; t++)
#pragma unroll
                    for (int o = 0; o < 2; o++) {
                        float* a4 = acc[t][g * 2 + o];
                        mma16816(a4, ah[t], bh[o], bh[o + 2]);   // hi*wh
                        mma16816(a4, al[t], bh[o], bh[o + 2]);   // lo*wh
                    }
            }
        }
    };

    // ---- prologue ----
    loadStage(0);
    if (nc > 1) loadStage(1);
    asm volatile("cp.async.wait_group %0;" :: "n"(1) : "memory");
    __syncthreads();

    // ---- mainloop ----
    for (int c = 0; c < nc; ++c) {
        compute(c);
        __syncthreads();
        if (c + 1 < nc) {
            if (c + 2 < nc) {
                loadStage(c + 2);
                asm volatile("cp.async.wait_group %0;" :: "n"(1) : "memory");
            } else {
                asm volatile("cp.async.wait_group %0;" :: "n"(0) : "memory");
            }
            __syncthreads();
        }
    }

    // ---- epilogue: C store + fused per-head attention scores ----
    float* sred = (float*)smem;                 // [0:128) src, [128:256) dst
#pragma unroll
    for (int i = tid; i < 256; i += 512) sred[i] = 0.f;

    float psum[2][2] = {{0.f, 0.f}, {0.f, 0.f}};
    float pdum[2][2] = {{0.f, 0.f}, {0.f, 0.f}};
#pragma unroll
    for (int t = 0; t < 2; t++) {
        int m0 = row0 + wm * 32 + t * 16 + (lane >> 2);
#pragma unroll
        for (int j = 0; j < 8; j++) {
            int cloc = wn * 64 + j * 8 + (lane & 3) * 2;
            int col = col0 + cloc;
            if (m0 < M)
                *(float2*)(C + (size_t)m0 * DH + col) =
                    make_float2(acc[t][j][0], acc[t][j][1]);
            if (m0 + 8 < M)
                *(float2*)(C + (size_t)(m0 + 8) * DH + col) =
                    make_float2(acc[t][j][2], acc[t][j][3]);
            float a0 = asrc[head * Cch + cloc], a1 = asrc[head * Cch + cloc + 1];
            float d0 = adst[head * Cch + cloc], d1 = adst[head * Cch + cloc + 1];
            psum[t][0] += acc[t][j][0] * a0 + acc[t][j][1] * a1;
            psum[t][1] += acc[t][j][2] * a0 + acc[t][j][3] * a1;
            pdum[t][0] += acc[t][j][0] * d0 + acc[t][j][1] * d1;
            pdum[t][1] += acc[t][j][2] * d0 + acc[t][j][3] * d1;
        }
    }
    // reduce over the 4 lanes of each quad (lane&3)
#pragma unroll
    for (int t = 0; t < 2; t++)
#pragma unroll
        for (int r2 = 0; r2 < 2; r2++) {
            psum[t][r2] += __shfl_xor_sync(0xffffffffu, psum[t][r2], 1);
            psum[t][r2] += __shfl_xor_sync(0xffffffffu, psum[t][r2], 2);
            pdum[t][r2] += __shfl_xor_sync(0xffffffffu, pdum[t][r2], 1);
            pdum[t][r2] += __shfl_xor_sync(0xffffffffu, pdum[t][r2], 2);
        }
    __syncthreads();            // sred zero-fill visible; stage reads long done
    if ((lane & 3) == 0) {
#pragma unroll
        for (int t = 0; t < 2; t++)
#pragma unroll
            for (int r2 = 0; r2 < 2; r2++) {
                int rl = wm * 32 + t * 16 + r2 * 8 + (lane >> 2);
                atomicAdd(&sred[rl],       psum[t][r2]);
                atomicAdd(&sred[128 + rl], pdum[t][r2]);
            }
    }
    __syncthreads();
#pragma unroll
    for (int r2 = tid; r2 < 128; r2 += 512) {
        int n = row0 + r2;
        if (n < M) {
            es[n * Hh + head] = sred[r2];
            ed[n * Hh + head] = sred[128 + r2];
        }
    }
}

// ---------------- fused softmax + gather aggregation -------------------------
__global__ __launch_bounds__(256)
void agg_kernel(const int* __restrict__ off, const int* __restrict__ csr,
                const float* __restrict__ es, const float* __restrict__ ed,
                const float* __restrict__ h, const float* __restrict__ bias,
                float* __restrict__ out,
                __half* __restrict__ ohi, __half* __restrict__ olo) {
    const int d = blockIdx.x;
    const int beg = off[d], end = off[d + 1];
    const int deg = end - beg;
    const int tid = threadIdx.x, wid = tid >> 5, lane = tid & 31;

    __shared__ float sm[4], ss[4];
    __shared__ float al[4][64];

    if (wid < 4) {
        const float edv = ed[d * 4 + wid];
        float mx = -INFINITY;
        for (int i = beg + lane; i < end; i += 32) {
            int s_ = csr[i];
            mx = fmaxf(mx, lrelu(es[s_ * 4 + wid] + edv));
        }
#pragma unroll
        for (int o = 16; o; o >>= 1)
            mx = fmaxf(mx, __shfl_xor_sync(0xffffffffu, mx, o));
        float su = 0.f;
        for (int i = beg + lane; i < end; i += 32) {
            int s_ = csr[i];
            su += expf(lrelu(es[s_ * 4 + wid] + edv) - mx);
        }
#pragma unroll
        for (int o = 16; o; o >>= 1)
            su += __shfl_xor_sync(0xffffffffu, su, o);
        if (lane == 0) { sm[wid] = mx; ss[wid] = su; }
    }
    __syncthreads();

    const int head = tid >> 6;
    float4 acc = make_float4(0.f, 0.f, 0.f, 0.f);

    for (int c0 = 0; c0 < deg; c0 += 64) {
        {
            int j = tid & 63, hh = tid >> 6;
            if (c0 + j < deg) {
                int s_ = csr[beg + c0 + j];
                float e = lrelu(es[s_ * 4 + hh] + ed[d * 4 + hh]);
                al[hh][j] = expf(e - sm[hh]) / (ss[hh] + 1e-16f);
            }
        }
        __syncthreads();
        int lim = min(64, deg - c0);
        for (int j = 0; j < lim; j++) {
            int s_ = csr[beg + c0 + j];
            float a = al[head][j];
            float4 v = *(const float4*)(h + (size_t)s_ * DH + tid * 4);
            acc.x = fmaf(a, v.x, acc.x);
            acc.y = fmaf(a, v.y, acc.y);
            acc.z = fmaf(a, v.z, acc.z);
            acc.w = fmaf(a, v.w, acc.w);
        }
        __syncthreads();
    }

    float4 bb = *(const float4*)(bias + tid * 4);
    acc.x = eluf(acc.x + bb.x);
    acc.y = eluf(acc.y + bb.y);
    acc.z = eluf(acc.z + bb.z);
    acc.w = eluf(acc.w + bb.w);

    if (ohi) {
        __half2 h0 = __floats2half2_rn(acc.x, acc.y);
        __half2 h1 = __floats2half2_rn(acc.z, acc.w);
        __half2 l0 = __floats2half2_rn(acc.x - __half2float(__low2half(h0)),
                                       acc.y - __half2float(__high2half(h0)));
        __half2 l1 = __floats2half2_rn(acc.z - __half2float(__low2half(h1)),
                                       acc.w - __half2float(__high2half(h1)));
        *(__half2*)(ohi + (size_t)d * DH + tid * 4)     = h0;
        *(__half2*)(ohi + (size_t)d * DH + tid * 4 + 2) = h1;
        *(__half2*)(olo + (size_t)d * DH + tid * 4)     = l0;
        *(__half2*)(olo + (size_t)d * DH + tid * 4 + 2) = l1;
    } else {
        *(float4*)(out + (size_t)d * DH + tid * 4) = acc;
    }
}

// ---------------- pooling accumulate (run-length over sorted batch) ----------
__global__ void pool_accum_kernel(const float* __restrict__ x, const int* __restrict__ batch,
                                  float* __restrict__ gsum, float* __restrict__ gmax) {
    int c  = blockIdx.x * 256 + threadIdx.x;
    int n0 = blockIdx.y * 128;
    int n1 = min(n0 + 128, Nn);
    float sum = 0.f, mx = -INFINITY;
    int cur = batch[n0];
    for (int n = n0; n < n1; ++n) {
        int g = batch[n];
        if (g != cur) {
            atomicAdd(&gsum[cur * DH + c], sum);
            atomicMaxF(&gmax[cur * DH + c], mx);
            sum = 0.f; mx = -INFINITY; cur = g;
        }
        float v = x[(size_t)n * DH + c];
        sum += v; if (v > mx) mx = v;
    }
    atomicAdd(&gsum[cur * DH + c], sum);
    atomicMaxF(&gmax[cur * DH + c], mx);
}

// ---------------- fused classifier: pool_final + fc1 + fc2 + fc3 -------------
__global__ __launch_bounds__(512)
void classifier_kernel(const float* __restrict__ gsum, const float* __restrict__ gmax,
                       const int* __restrict__ cnt,
                       const float* __restrict__ Wc1, const float* __restrict__ bc1,
                       const float* __restrict__ Wc2, const float* __restrict__ bc2,
                       const float* __restrict__ Wc3, const float* __restrict__ bc3,
                       float* __restrict__ out) {
    __shared__ float pool[2 * DH];
    __shared__ float f1[512];
    __shared__ float f2[256];
    const int g = blockIdx.x, tid = threadIdx.x;

    float cf = (float)cnt[g]; if (cf < 1.f) cf = 1.f;
    for (int c = tid; c < DH; c += 512) {
        pool[c] = gsum[g * DH + c] / cf;
        float mv = gmax[g * DH + c];
        pool[DH + c] = isfinite(mv) ? mv : 0.f;
    }
    __syncthreads();

    {   // fc1: 2048 -> 512, relu
        float a = bc1[tid];
#pragma unroll 8
        for (int k = 0; k < 2 * DH; k++)
            a = fmaf(pool[k], Wc1[(size_t)k * 512 + tid], a);
        f1[tid] = fmaxf(a, 0.f);
    }
    __syncthreads();

    if (tid < 256) {   // fc2: 512 -> 256, relu
        float a = bc2[tid];
#pragma unroll 8
        for (int k = 0; k < 512; k++)
            a = fmaf(f1[k], Wc2[(size_t)k * 256 + tid], a);
        f2[tid] = fmaxf(a, 0.f);
    }
    __syncthreads();

    if (tid < 5) {     // fc3: 256 -> 5
        float a = bc3[tid];
        for (int k = 0; k < 256; k++)
            a = fmaf(f2[k], Wc3[k * 5 + tid], a);
        out[g * 5 + tid] = a;
    }
}

// ---------------- host -------------------------------------------------------
extern "C" void kernel_launch(void* const* d_in, const int* in_sizes, int n_in,
                              void* d_out, int out_size) {
    (void)in_sizes; (void)n_in; (void)out_size;
    const float* x   = (const float*)d_in[0];
    const int*   ei  = (const int*)  d_in[1];
    const int*   bat = (const int*)  d_in[2];
    const float* W1  = (const float*)d_in[3];
    const float* as1 = (const float*)d_in[4];
    const float* ad1 = (const float*)d_in[5];
    const float* b1  = (const float*)d_in[6];
    const float* W2  = (const float*)d_in[7];
    const float* as2 = (const float*)d_in[8];
    const float* ad2 = (const float*)d_in[9];
    const float* b2  = (const float*)d_in[10];
    const float* Wc1 = (const float*)d_in[11];
    const float* bc1 = (const float*)d_in[12];
    const float* Wc2 = (const float*)d_in[13];
    const float* bc2 = (const float*)d_in[14];
    const float* Wc3 = (const float*)d_in[15];
    const float* bc3 = (const float*)d_in[16];
    float* out = (float*)d_out;

    float *ph, *px, *pes, *ped, *psum, *pmax;
    int *pcnt, *pdeg, *poff, *pcur, *pcsr;
    __half *pwth, *pahi, *palo;
    cudaGetSymbolAddress((void**)&ph,   g_h);
    cudaGetSymbolAddress((void**)&px,   g_x);
    cudaGetSymbolAddress((void**)&pes,  g_esrc);
    cudaGetSymbolAddress((void**)&ped,  g_edst);
    cudaGetSymbolAddress((void**)&psum, g_sum);
    cudaGetSymbolAddress((void**)&pmax, g_max);
    cudaGetSymbolAddress((void**)&pcnt, g_cnt);
    cudaGetSymbolAddress((void**)&pwth, g_wth);
    cudaGetSymbolAddress((void**)&pahi, g_ahi);
    cudaGetSymbolAddress((void**)&palo, g_alo);
    cudaGetSymbolAddress((void**)&pdeg, g_deg);
    cudaGetSymbolAddress((void**)&poff, g_off);
    cudaGetSymbolAddress((void**)&pcur, g_cur);
    cudaGetSymbolAddress((void**)&pcsr, g_csr);

    cudaFuncSetAttribute(gemm_mma_kernel,
                         cudaFuncAttributeMaxDynamicSharedMemorySize, GEMM_SMEM);

    const int* src = ei;
    const int* dst = ei + Ee;

    const int GRID_E = (EP + 255) / 256;
    const int GRID_I = (INIT_TOT + 255) / 256;
    const dim3 gemm_grid(DH / 256, (Nn + 127) / 128);   // (4, 391)

    // ---- CSR build + pooling init (graph is identical for both layers) ----
    csr_zero_kernel<<<GRID_I, 256>>>(pdeg, pcur, psum, pmax, pcnt);
    csr_hist_kernel<<<GRID_E, 256>>>(dst, pdeg, bat, pcnt);
    csr_scan_kernel<<<1, 1024>>>(pdeg, poff);
    csr_fill_kernel<<<GRID_E, 256>>>(src, dst, poff, pcur, pcsr);

    // ---- GAT layer 1 ----
    wsplit_kernel<<<(DIN * DH + 255) / 256, 256>>>(W1, pwth, DIN);
    asplit_kernel<<<(Nn * DIN + 255) / 256, 256>>>(x, pahi, palo, Nn * DIN);
    gemm_mma_kernel<<<gemm_grid, 512, GEMM_SMEM>>>(pahi, palo, pwth,
                                                   ph, Nn, DIN,
                                                   as1, ad1, pes, ped);
    agg_kernel<<<Nn, 256>>>(poff, pcsr, pes, ped, ph, b1, (float*)0, pahi, palo);

    // ---- GAT layer 2 ----
    wsplit_kernel<<<(DH * DH + 255) / 256, 256>>>(W2, pwth, DH);
    gemm_mma_kernel<<<gemm_grid, 512, GEMM_SMEM>>>(pahi, palo, pwth,
                                                   ph, Nn, DH,
                                                   as2, ad2, pes, ped);
    agg_kernel<<<Nn, 256>>>(poff, pcsr, pes, ped, ph, b2, px,
                            (__half*)0, (__half*)0);

    // ---- pooling + classifier ----
    pool_accum_kernel<<<dim3(DH / 256, (Nn + 127) / 128), 256>>>(px, bat, psum, pmax);
    classifier_kernel<<<Gg, 512>>>(psum, pmax, pcnt,
                                   Wc1, bc1, Wc2, bc2, Wc3, bc3, out);
}

// round 17
// speedup vs baseline: 1.6476x; 1.3301x over previous
#include <cuda_runtime.h>
#include <cuda_fp16.h>
#include <math.h>
#include <stdint.h>

#define Nn   50000
#define Ee   200000
#define EP   (Ee + Nn)      // 250000 edges incl. self loops
#define Gg   64
#define Hh   4
#define Cch  256
#define DH   1024
#define DIN  768

// ---------------- scratch (device globals; no allocation allowed) ----------
__device__ float g_h  [(size_t)Nn * DH];   // x @ W  (current layer)
__device__ float g_x  [(size_t)Nn * DH];   // layer-2 output (post ELU)
__device__ float g_esrc[Nn * Hh];
__device__ float g_edst[Nn * Hh];
__device__ float g_sum [Gg * DH];
__device__ float g_max [Gg * DH];
__device__ int   g_cnt [Gg];
// transposed fp16 weights: Wt[n][k]  (single rounded copy)
__device__ __half g_wth[(size_t)DH * DH];
// fp16 activations (GEMM A operand)
__device__ __half g_ah[(size_t)Nn * DH];
// CSR by destination
__device__ int g_deg[Nn];
__device__ int g_off[Nn + 1];
__device__ int g_cur[Nn];
__device__ int g_csr[EP];          // src node per slot

// ---------------- helpers ---------------------------------------------------
__device__ __forceinline__ float lrelu(float x) { return x > 0.f ? x : 0.2f * x; }
__device__ __forceinline__ float eluf (float x) { return x > 0.f ? x : expm1f(x); }

__device__ __forceinline__ void atomicMaxF(float* a, float v) {
    if (v >= 0.f) atomicMax((int*)a, __float_as_int(v));
    else          atomicMin((unsigned int*)a, __float_as_uint(v));
}

__device__ __forceinline__ uint32_t smem_u32(const void* p) {
    uint32_t a;
    asm("{ .reg .u64 t; cvta.to.shared.u64 t, %1; cvt.u32.u64 %0, t; }"
        : "=r"(a) : "l"(p));
    return a;
}

__device__ __forceinline__ void ldm4(uint32_t* r, uint32_t addr) {
    asm volatile("ldmatrix.sync.aligned.m8n8.x4.shared.b16 {%0,%1,%2,%3}, [%4];"
                 : "=r"(r[0]), "=r"(r[1]), "=r"(r[2]), "=r"(r[3]) : "r"(addr));
}

__device__ __forceinline__ void mma16816(float* c, const uint32_t* a,
                                         uint32_t b0, uint32_t b1) {
    asm volatile(
        "mma.sync.aligned.m16n8k16.row.col.f32.f16.f16.f32 "
        "{%0,%1,%2,%3}, {%4,%5,%6,%7}, {%8,%9}, {%0,%1,%2,%3};"
        : "+f"(c[0]), "+f"(c[1]), "+f"(c[2]), "+f"(c[3])
        : "r"(a[0]), "r"(a[1]), "r"(a[2]), "r"(a[3]), "r"(b0), "r"(b1));
}

#define CPA16(dst, src) \
    asm volatile("cp.async.cg.shared.global [%0], [%1], 16;" \
                 :: "r"(dst), "l"(src) : "memory")
#define CPA16Z(dst, src, szr) \
    asm volatile("cp.async.cg.shared.global [%0], [%1], 16, %2;" \
                 :: "r"(dst), "l"(src), "r"(szr) : "memory")

// ---------------- CSR build (+ pooling init folded in) -----------------------
#define INIT_TOT (Gg * DH)          // 65536 >= Nn
__global__ void csr_zero_kernel(int* __restrict__ deg, int* __restrict__ cur,
                                float* __restrict__ gsum, float* __restrict__ gmax,
                                int* __restrict__ cnt) {
    int i = blockIdx.x * 256 + threadIdx.x;
    if (i < Nn) { deg[i] = 0; cur[i] = 0; }
    if (i < INIT_TOT) { gsum[i] = 0.f; gmax[i] = -INFINITY; }
    if (i < Gg) cnt[i] = 0;
}

__global__ void csr_hist_kernel(const int* __restrict__ dst, int* __restrict__ deg,
                                const int* __restrict__ batch, int* __restrict__ cnt) {
    int i = blockIdx.x * 256 + threadIdx.x;
    if (i < Nn) atomicAdd(&cnt[batch[i]], 1);
    if (i >= EP) return;
    int d_ = (i < Ee) ? dst[i] : (i - Ee);
    atomicAdd(&deg[d_], 1);
}

__global__ void csr_scan_kernel(const int* __restrict__ deg, int* __restrict__ off) {
    __shared__ int bs[1024];
    const int t = threadIdx.x;
    const int per = (Nn + 1023) / 1024;        // 49
    const int b0 = t * per;
    int loc = 0;
    for (int i = 0; i < per; i++) {
        int idx = b0 + i;
        if (idx < Nn) loc += deg[idx];
    }
    bs[t] = loc;
    __syncthreads();
    for (int o = 1; o < 1024; o <<= 1) {
        int v = (t >= o) ? bs[t - o] : 0;
        __syncthreads();
        bs[t] += v;
        __syncthreads();
    }
    int run = t ? bs[t - 1] : 0;
    for (int i = 0; i < per; i++) {
        int idx = b0 + i;
        if (idx < Nn) { off[idx] = run; run += deg[idx]; }
    }
    if (t == 1023) off[Nn] = run;
}

__global__ void csr_fill_kernel(const int* __restrict__ src, const int* __restrict__ dst,
                                const int* __restrict__ off, int* __restrict__ cur,
                                int* __restrict__ csr) {
    int i = blockIdx.x * 256 + threadIdx.x;
    if (i >= EP) return;
    int s_, d_;
    if (i < Ee) { s_ = src[i]; d_ = dst[i]; } else { s_ = d_ = i - Ee; }
    int pos = off[d_] + atomicAdd(&cur[d_], 1);
    csr[pos] = s_;
}

// ---------------- converts ---------------------------------------------------
__global__ void wsplit_kernel(const float* __restrict__ W,
                              __half* __restrict__ hi, int K) {
    int idx = blockIdx.x * 256 + threadIdx.x;
    if (idx >= K * DH) return;
    int n = idx & (DH - 1), k = idx >> 10;   // W[k][n], row-major (K, 1024)
    hi[(size_t)n * K + k] = __float2half_rn(W[idx]);
}

__global__ void aconv_kernel(const float* __restrict__ A,
                             __half* __restrict__ hi, int total) {
    int idx = blockIdx.x * 256 + threadIdx.x;
    if (idx >= total) return;
    hi[idx] = __float2half_rn(A[idx]);
}

// ---------------- tensor-core GEMM via mma.sync (fp16) ----------------------
// C[M,1024] = A[M,K] @ W[K,1024]; A and W rounded once to fp16, fp32 accum.
// Tile 128x256, 512 threads, K-chunk 64, 2-stage cp.async, fused score epi.
// stage (48KB): Ah[16K] Bh[32K]; 128B SW128 rows.
#define STAGE_B 49152u
#define GEMM_SMEM (2 * 49152)

__global__ __launch_bounds__(512, 1)
void gemm_mma_kernel(const __half* __restrict__ Ahg,
                     const __half* __restrict__ Bh_,
                     float* __restrict__ C, int M, int K,
                     const float* __restrict__ asrc,
                     const float* __restrict__ adst,
                     float* __restrict__ es, float* __restrict__ ed) {
    extern __shared__ __align__(1024) char smem[];
    const int tid = threadIdx.x, wid = tid >> 5, lane = tid & 31;
    const int wm = wid & 3, wn = wid >> 2;
    const int lr = lane & 15, lh = lane >> 4;
    const int row0 = blockIdx.y * 128, col0 = blockIdx.x * 256;
    const int head = blockIdx.x;               // 256-wide col tile == head
    const uint32_t sb = smem_u32(smem);
    const int nc = K >> 6;

    float acc[2][8][4];
#pragma unroll
    for (int t = 0; t < 2; t++)
#pragma unroll
        for (int j = 0; j < 8; j++)
#pragma unroll
            for (int q = 0; q < 4; q++) acc[t][j][q] = 0.f;

    auto loadStage = [&](int ck) {
        uint32_t st = sb + (uint32_t)(ck & 1) * STAGE_B;
        const __half* Ah = Ahg + (size_t)row0 * K + ck * 64;
#pragma unroll
        for (int u = tid; u < 1024; u += 512) {
            int r = u >> 3, c = u & 7;
            uint32_t d = st + (uint32_t)(r * 128) + (uint32_t)((c ^ (r & 7)) << 4);
            uint32_t sz = (row0 + r < M) ? 16u : 0u;
            CPA16Z(d, Ah + (size_t)r * K + c * 8, sz);
        }
        const __half* Bp = Bh_ + (size_t)col0 * K + ck * 64;
#pragma unroll
        for (int u = tid; u < 2048; u += 512) {
            int r = u >> 3, c = u & 7;
            uint32_t d = st + 16384u + (uint32_t)(r * 128) +
                         (uint32_t)((c ^ (r & 7)) << 4);
            CPA16(d, Bp + (size_t)r * K + c * 8);
        }
        asm volatile("cp.async.commit_group;" ::: "memory");
    };

    auto compute = [&](int ck) {
        uint32_t base = sb + (uint32_t)(ck & 1) * STAGE_B;
#pragma unroll
        for (int ks = 0; ks < 4; ks++) {
            uint32_t c16 = (uint32_t)(ks * 2 + lh);
            uint32_t ah[2][4];
#pragma unroll
            for (int t = 0; t < 2; t++) {
                int row = wm * 32 + t * 16 + lr;
                uint32_t ad = base + (uint32_t)(row * 128) +
                              ((c16 ^ (uint32_t)(row & 7)) << 4);
                ldm4(ah[t], ad);
            }
#pragma unroll
            for (int g = 0; g < 4; g++) {
                int row = wn * 64 + g * 16 + lr;
                uint32_t bd = base + 16384u + (uint32_t)(row * 128) +
                              ((c16 ^ (uint32_t)(row & 7)) << 4);
                uint32_t bh[4];
                ldm4(bh, bd);
#pragma unroll
                for (int t = 0; t < 2; t++)
#pragma unroll
                    for (int o = 0; o < 2; o++)
                        mma16816(acc[t][g * 2 + o], ah[t], bh[o], bh[o + 2]);
            }
        }
    };

    // ---- prologue ----
    loadStage(0);
    if (nc > 1) loadStage(1);
    asm volatile("cp.async.wait_group %0;" :: "n"(1) : "memory");
    __syncthreads();

    // ---- mainloop ----
    for (int c = 0; c < nc; ++c) {
        compute(c);
        __syncthreads();
        if (c + 1 < nc) {
            if (c + 2 < nc) {
                loadStage(c + 2);
                asm volatile("cp.async.wait_group %0;" :: "n"(1) : "memory");
            } else {
                asm volatile("cp.async.wait_group %0;" :: "n"(0) : "memory");
            }
            __syncthreads();
        }
    }

    // ---- epilogue: C store + fused per-head attention scores ----
    float* sred = (float*)smem;                 // [0:128) src, [128:256) dst
#pragma unroll
    for (int i = tid; i < 256; i += 512) sred[i] = 0.f;

    float psum[2][2] = {{0.f, 0.f}, {0.f, 0.f}};
    float pdum[2][2] = {{0.f, 0.f}, {0.f, 0.f}};
#pragma unroll
    for (int t = 0; t < 2; t++) {
        int m0 = row0 + wm * 32 + t * 16 + (lane >> 2);
#pragma unroll
        for (int j = 0; j < 8; j++) {
            int cloc = wn * 64 + j * 8 + (lane & 3) * 2;
            int col = col0 + cloc;
            if (m0 < M)
                *(float2*)(C + (size_t)m0 * DH + col) =
                    make_float2(acc[t][j][0], acc[t][j][1]);
            if (m0 + 8 < M)
                *(float2*)(C + (size_t)(m0 + 8) * DH + col) =
                    make_float2(acc[t][j][2], acc[t][j][3]);
            float a0 = asrc[head * Cch + cloc], a1 = asrc[head * Cch + cloc + 1];
            float d0 = adst[head * Cch + cloc], d1 = adst[head * Cch + cloc + 1];
            psum[t][0] += acc[t][j][0] * a0 + acc[t][j][1] * a1;
            psum[t][1] += acc[t][j][2] * a0 + acc[t][j][3] * a1;
            pdum[t][0] += acc[t][j][0] * d0 + acc[t][j][1] * d1;
            pdum[t][1] += acc[t][j][2] * d0 + acc[t][j][3] * d1;
        }
    }
    // reduce over the 4 lanes of each quad (lane&3)
#pragma unroll
    for (int t = 0; t < 2; t++)
#pragma unroll
        for (int r2 = 0; r2 < 2; r2++) {
            psum[t][r2] += __shfl_xor_sync(0xffffffffu, psum[t][r2], 1);
            psum[t][r2] += __shfl_xor_sync(0xffffffffu, psum[t][r2], 2);
            pdum[t][r2] += __shfl_xor_sync(0xffffffffu, pdum[t][r2], 1);
            pdum[t][r2] += __shfl_xor_sync(0xffffffffu, pdum[t][r2], 2);
        }
    __syncthreads();            // sred zero-fill visible; stage reads long done
    if ((lane & 3) == 0) {
#pragma unroll
        for (int t = 0; t < 2; t++)
#pragma unroll
            for (int r2 = 0; r2 < 2; r2++) {
                int rl = wm * 32 + t * 16 + r2 * 8 + (lane >> 2);
                atomicAdd(&sred[rl],       psum[t][r2]);
                atomicAdd(&sred[128 + rl], pdum[t][r2]);
            }
    }
    __syncthreads();
#pragma unroll
    for (int r2 = tid; r2 < 128; r2 += 512) {
        int n = row0 + r2;
        if (n < M) {
            es[n * Hh + head] = sred[r2];
            ed[n * Hh + head] = sred[128 + r2];
        }
    }
}

// ---------------- fused softmax + gather aggregation -------------------------
__global__ __launch_bounds__(256)
void agg_kernel(const int* __restrict__ off, const int* __restrict__ csr,
                const float* __restrict__ es, const float* __restrict__ ed,
                const float* __restrict__ h, const float* __restrict__ bias,
                float* __restrict__ out,
                __half* __restrict__ ohi) {
    const int d = blockIdx.x;
    const int beg = off[d], end = off[d + 1];
    const int deg = end - beg;
    const int tid = threadIdx.x, wid = tid >> 5, lane = tid & 31;

    __shared__ float sm[4], ss[4];
    __shared__ float al[4][64];

    if (wid < 4) {
        const float edv = ed[d * 4 + wid];
        float mx = -INFINITY;
        for (int i = beg + lane; i < end; i += 32) {
            int s_ = csr[i];
            mx = fmaxf(mx, lrelu(es[s_ * 4 + wid] + edv));
        }
#pragma unroll
        for (int o = 16; o; o >>= 1)
            mx = fmaxf(mx, __shfl_xor_sync(0xffffffffu, mx, o));
        float su = 0.f;
        for (int i = beg + lane; i < end; i += 32) {
            int s_ = csr[i];
            su += expf(lrelu(es[s_ * 4 + wid] + edv) - mx);
        }
#pragma unroll
        for (int o = 16; o; o >>= 1)
            su += __shfl_xor_sync(0xffffffffu, su, o);
        if (lane == 0) { sm[wid] = mx; ss[wid] = su; }
    }
    __syncthreads();

    const int head = tid >> 6;
    float4 acc = make_float4(0.f, 0.f, 0.f, 0.f);

    for (int c0 = 0; c0 < deg; c0 += 64) {
        {
            int j = tid & 63, hh = tid >> 6;
            if (c0 + j < deg) {
                int s_ = csr[beg + c0 + j];
                float e = lrelu(es[s_ * 4 + hh] + ed[d * 4 + hh]);
                al[hh][j] = expf(e - sm[hh]) / (ss[hh] + 1e-16f);
            }
        }
        __syncthreads();
        int lim = min(64, deg - c0);
        for (int j = 0; j < lim; j++) {
            int s_ = csr[beg + c0 + j];
            float a = al[head][j];
            float4 v = *(const float4*)(h + (size_t)s_ * DH + tid * 4);
            acc.x = fmaf(a, v.x, acc.x);
            acc.y = fmaf(a, v.y, acc.y);
            acc.z = fmaf(a, v.z, acc.z);
            acc.w = fmaf(a, v.w, acc.w);
        }
        __syncthreads();
    }

    float4 bb = *(const float4*)(bias + tid * 4);
    acc.x = eluf(acc.x + bb.x);
    acc.y = eluf(acc.y + bb.y);
    acc.z = eluf(acc.z + bb.z);
    acc.w = eluf(acc.w + bb.w);

    if (ohi) {
        __half2 h0 = __floats2half2_rn(acc.x, acc.y);
        __half2 h1 = __floats2half2_rn(acc.z, acc.w);
        *(__half2*)(ohi + (size_t)d * DH + tid * 4)     = h0;
        *(__half2*)(ohi + (size_t)d * DH + tid * 4 + 2) = h1;
    } else {
        *(float4*)(out + (size_t)d * DH + tid * 4) = acc;
    }
}

// ---------------- pooling accumulate (run-length over sorted batch) ----------
__global__ void pool_accum_kernel(const float* __restrict__ x, const int* __restrict__ batch,
                                  float* __restrict__ gsum, float* __restrict__ gmax) {
    int c  = blockIdx.x * 256 + threadIdx.x;
    int n0 = blockIdx.y * 128;
    int n1 = min(n0 + 128, Nn);
    float sum = 0.f, mx = -INFINITY;
    int cur = batch[n0];
    for (int n = n0; n < n1; ++n) {
        int g = batch[n];
        if (g != cur) {
            atomicAdd(&gsum[cur * DH + c], sum);
            atomicMaxF(&gmax[cur * DH + c], mx);
            sum = 0.f; mx = -INFINITY; cur = g;
        }
        float v = x[(size_t)n * DH + c];
        sum += v; if (v > mx) mx = v;
    }
    atomicAdd(&gsum[cur * DH + c], sum);
    atomicMaxF(&gmax[cur * DH + c], mx);
}

// ---------------- fused classifier: pool_final + fc1 + fc2 + fc3 -------------
__global__ __launch_bounds__(512)
void classifier_kernel(const float* __restrict__ gsum, const float* __restrict__ gmax,
                       const int* __restrict__ cnt,
                       const float* __restrict__ Wc1, const float* __restrict__ bc1,
                       const float* __restrict__ Wc2, const float* __restrict__ bc2,
                       const float* __restrict__ Wc3, const float* __restrict__ bc3,
                       float* __restrict__ out) {
    __shared__ float pool[2 * DH];
    __shared__ float f1[512];
    __shared__ float f2[256];
    const int g = blockIdx.x, tid = threadIdx.x;

    float cf = (float)cnt[g]; if (cf < 1.f) cf = 1.f;
    for (int c = tid; c < DH; c += 512) {
        pool[c] = gsum[g * DH + c] / cf;
        float mv = gmax[g * DH + c];
        pool[DH + c] = isfinite(mv) ? mv : 0.f;
    }
    __syncthreads();

    {   // fc1: 2048 -> 512, relu
        float a = bc1[tid];
#pragma unroll 8
        for (int k = 0; k < 2 * DH; k++)
            a = fmaf(pool[k], Wc1[(size_t)k * 512 + tid], a);
        f1[tid] = fmaxf(a, 0.f);
    }
    __syncthreads();

    if (tid < 256) {   // fc2: 512 -> 256, relu
        float a = bc2[tid];
#pragma unroll 8
        for (int k = 0; k < 512; k++)
            a = fmaf(f1[k], Wc2[(size_t)k * 256 + tid], a);
        f2[tid] = fmaxf(a, 0.f);
    }
    __syncthreads();

    if (tid < 5) {     // fc3: 256 -> 5
        float a = bc3[tid];
        for (int k = 0; k < 256; k++)
            a = fmaf(f2[k], Wc3[k * 5 + tid], a);
        out[g * 5 + tid] = a;
    }
}

// ---------------- host -------------------------------------------------------
extern "C" void kernel_launch(void* const* d_in, const int* in_sizes, int n_in,
                              void* d_out, int out_size) {
    (void)in_sizes; (void)n_in; (void)out_size;
    const float* x   = (const float*)d_in[0];
    const int*   ei  = (const int*)  d_in[1];
    const int*   bat = (const int*)  d_in[2];
    const float* W1  = (const float*)d_in[3];
    const float* as1 = (const float*)d_in[4];
    const float* ad1 = (const float*)d_in[5];
    const float* b1  = (const float*)d_in[6];
    const float* W2  = (const float*)d_in[7];
    const float* as2 = (const float*)d_in[8];
    const float* ad2 = (const float*)d_in[9];
    const float* b2  = (const float*)d_in[10];
    const float* Wc1 = (const float*)d_in[11];
    const float* bc1 = (const float*)d_in[12];
    const float* Wc2 = (const float*)d_in[13];
    const float* bc2 = (const float*)d_in[14];
    const float* Wc3 = (const float*)d_in[15];
    const float* bc3 = (const float*)d_in[16];
    float* out = (float*)d_out;

    float *ph, *px, *pes, *ped, *psum, *pmax;
    int *pcnt, *pdeg, *poff, *pcur, *pcsr;
    __half *pwth, *pah;
    cudaGetSymbolAddress((void**)&ph,   g_h);
    cudaGetSymbolAddress((void**)&px,   g_x);
    cudaGetSymbolAddress((void**)&pes,  g_esrc);
    cudaGetSymbolAddress((void**)&ped,  g_edst);
    cudaGetSymbolAddress((void**)&psum, g_sum);
    cudaGetSymbolAddress((void**)&pmax, g_max);
    cudaGetSymbolAddress((void**)&pcnt, g_cnt);
    cudaGetSymbolAddress((void**)&pwth, g_wth);
    cudaGetSymbolAddress((void**)&pah,  g_ah);
    cudaGetSymbolAddress((void**)&pdeg, g_deg);
    cudaGetSymbolAddress((void**)&poff, g_off);
    cudaGetSymbolAddress((void**)&pcur, g_cur);
    cudaGetSymbolAddress((void**)&pcsr, g_csr);

    cudaFuncSetAttribute(gemm_mma_kernel,
                         cudaFuncAttributeMaxDynamicSharedMemorySize, GEMM_SMEM);

    const int* src = ei;
    const int* dst = ei + Ee;

    const int GRID_E = (EP + 255) / 256;
    const int GRID_I = (INIT_TOT + 255) / 256;
    const dim3 gemm_grid(DH / 256, (Nn + 127) / 128);   // (4, 391)

    // ---- CSR build + pooling init (graph is identical for both layers) ----
    csr_zero_kernel<<<GRID_I, 256>>>(pdeg, pcur, psum, pmax, pcnt);
    csr_hist_kernel<<<GRID_E, 256>>>(dst, pdeg, bat, pcnt);
    csr_scan_kernel<<<1, 1024>>>(pdeg, poff);
    csr_fill_kernel<<<GRID_E, 256>>>(src, dst, poff, pcur, pcsr);

    // ---- GAT layer 1 ----
    wsplit_kernel<<<(DIN * DH + 255) / 256, 256>>>(W1, pwth, DIN);
    aconv_kernel<<<(Nn * DIN + 255) / 256, 256>>>(x, pah, Nn * DIN);
    gemm_mma_kernel<<<gemm_grid, 512, GEMM_SMEM>>>(pah, pwth, ph, Nn, DIN,
                                                   as1, ad1, pes, ped);
    agg_kernel<<<Nn, 256>>>(poff, pcsr, pes, ped, ph, b1, (float*)0, pah);

    // ---- GAT layer 2 ----
    wsplit_kernel<<<(DH * DH + 255) / 256, 256>>>(W2, pwth, DH);
    gemm_mma_kernel<<<gemm_grid, 512, GEMM_SMEM>>>(pah, pwth, ph, Nn, DH,
                                                   as2, ad2, pes, ped);
    agg_kernel<<<Nn, 256>>>(poff, pcsr, pes, ped, ph, b2, px, (__half*)0);

    // ---- pooling + classifier ----
    pool_accum_kernel<<<dim3(DH / 256, (Nn + 127) / 128), 256>>>(px, bat, psum, pmax);
    classifier_kernel<<<Gg, 512>>>(psum, pmax, pcnt,
                                   Wc1, bc1, Wc2, bc2, Wc3, bc3, out);
}